// round 14
// baseline (speedup 1.0000x reference)
#include <cuda_runtime.h>
#include <cuda_fp16.h>
#include <cstdint>

// Problem constants
#define BB   64
#define SRC  2048
#define ENCD 1024
#define UU   1024
#define EE   512
#define VV   32000
#define IN0  (ENCD + EE)        // 1536
#define MROWS (BB * SRC)        // 131072
#define XSEG (BB * 3 * UU)      // one gate-preact buffer
#define NSPLIT 8

// ---------------- scratch (device globals; no allocation allowed) -----------
__device__ float  g_h[BB * UU];
__device__ __half g_encH[(size_t)MROWS * ENCD];   // enc in fp16 (256MB)
__device__ __half g_WcTH[ENCD * UU];              // Wc transposed fp16
__device__ float  g_s[2 * MROWS];                 // per-jhalf partial scores
__device__ float  g_w[BB * SRC];                  // softmax weights
__device__ float  g_ctxp[16][BB][ENCD];
__device__ float  g_xin[BB * IN0];
__device__ float  g_xgp[NSPLIT][2][XSEG];         // split-K partials
__device__ float  g_y[BB * 2 * UU];

// ---------------- helpers ----------------------------------------------------
__device__ __forceinline__ unsigned f2tf32(float f) {
    unsigned u;
    asm("cvt.rna.tf32.f32 %0, %1;" : "=r"(u) : "f"(f));
    return u;
}
__device__ __forceinline__ float htanh(float x) {
    float r;
    asm("tanh.approx.f32 %0, %1;" : "=f"(r) : "f"(x));
    return r;
}
__device__ __forceinline__ uint32_t smem_u32(const void* p) {
    uint32_t a;
    asm("{ .reg .u64 t; cvta.to.shared.u64 t, %1; cvt.u32.u64 %0, t; }" : "=r"(a) : "l"(p));
    return a;
}
__device__ __forceinline__ void cp16(uint32_t dst, const void* src) {
    asm volatile("cp.async.cg.shared.global [%0], [%1], 16;\n" :: "r"(dst), "l"(src));
}
#define CP_COMMIT() asm volatile("cp.async.commit_group;" ::: "memory")
#define CP_WAIT0()  asm volatile("cp.async.wait_group 0;" ::: "memory")
#define CP_WAIT1()  asm volatile("cp.async.wait_group 1;" ::: "memory")
#define CP_WAIT2()  asm volatile("cp.async.wait_group 2;" ::: "memory")

#define LDSM4(r0, r1, r2, r3, addr)                                              \
    asm volatile("ldmatrix.sync.aligned.m8n8.x4.shared.b16 {%0,%1,%2,%3}, [%4];" \
                 : "=r"(r0), "=r"(r1), "=r"(r2), "=r"(r3) : "r"(addr))

// fp16 mma m16n8k16 with fp32 accumulate
#define MMA_F16(c, a, b)                                                         \
    asm volatile(                                                                \
        "mma.sync.aligned.m16n8k16.row.col.f32.f16.f16.f32 "                     \
        "{%0,%1,%2,%3},{%4,%5,%6,%7},{%8,%9},{%0,%1,%2,%3};\n"                   \
        : "+f"((c)[0]), "+f"((c)[1]), "+f"((c)[2]), "+f"((c)[3])                 \
        : "r"((a)[0]), "r"((a)[1]), "r"((a)[2]), "r"((a)[3]),                    \
          "r"((b)[0]), "r"((b)[1]))

// tf32 mma m16n8k8 (small GEMMs)
#define MMA_TF32(c, a, b)                                                        \
    asm volatile(                                                                \
        "mma.sync.aligned.m16n8k8.row.col.f32.tf32.tf32.f32 "                    \
        "{%0,%1,%2,%3},{%4,%5,%6,%7},{%8,%9},{%0,%1,%2,%3};\n"                   \
        : "+f"((c)[0]), "+f"((c)[1]), "+f"((c)[2]), "+f"((c)[3])                 \
        : "r"((a)[0]), "r"((a)[1]), "r"((a)[2]), "r"((a)[3]),                    \
          "r"((b)[0]), "r"((b)[1]))

// ---------------- k_prep : Wc transpose | h = state@Wh+bh (4-way col split) --
#define PREP_TR_BLKS 1024
#define PREP_TOTAL (PREP_TR_BLKS + BB * 4)

__global__ void k_prep(const float* __restrict__ Wc,
                       const float* __restrict__ state, const float* __restrict__ Wh,
                       const float* __restrict__ bh) {
    __shared__ float sbuf[32 * 33];
    const int bx = blockIdx.x, tid = threadIdx.x;

    if (bx < PREP_TR_BLKS) {
        int j0 = (bx & 31) * 32, k0 = (bx >> 5) * 32;
        int lx = tid & 31, ly = tid >> 5;
        float (*t)[33] = reinterpret_cast<float(*)[33]>(sbuf);
#pragma unroll
        for (int i = 0; i < 4; i++) {
            int kk = ly + i * 8;
            t[kk][lx] = Wc[(size_t)(k0 + kk) * UU + j0 + lx];
        }
        __syncthreads();
#pragma unroll
        for (int i = 0; i < 4; i++) {
            int jj = ly + i * 8;
            g_WcTH[(size_t)(j0 + jj) * ENCD + k0 + lx] = __float2half_rn(t[lx][jj]);
        }
    } else {
        int idx = bx - PREP_TR_BLKS;
        int b = idx >> 2, jq = idx & 3;
        float* ss = sbuf;
        for (int i = tid; i < UU; i += 256) ss[i] = state[b * UU + i];
        __syncthreads();
        int col = jq * 256 + tid;
        float a0 = 0.f, a1 = 0.f, a2 = 0.f, a3 = 0.f;
#pragma unroll 2
        for (int k = 0; k < UU; k += 4) {
            a0 += ss[k] * Wh[(size_t)k * UU + col];
            a1 += ss[k + 1] * Wh[(size_t)(k + 1) * UU + col];
            a2 += ss[k + 2] * Wh[(size_t)(k + 2) * UU + col];
            a3 += ss[k + 3] * Wh[(size_t)(k + 3) * UU + col];
        }
        g_h[b * UU + col] = (a0 + a1) + (a2 + a3) + bh[col];
    }
}

// ---------------- k_score : fp16 mma, j-split grid (1024 x 2) ---------------
// each CTA: 128-row block x 4 j-tiles (one j-half); 64 iterations
#define SKW 36                   // smem row stride in words (32 data + 4 pad)
#define STGW (128 * SKW)
#define STGB (STGW * 4)          // 18432 bytes per stage
#define SC_SMEM ((3 + 2) * STGB + (512 + 512 + 128) * 4)

__global__ __launch_bounds__(256, 2) void k_score(const float* __restrict__ enc,
                                                  const float* __restrict__ bc,
                                                  const float* __restrict__ Ws) {
    extern __shared__ char dsm[];
    uint32_t* sAp = reinterpret_cast<uint32_t*>(dsm);          // 3 stages
    uint32_t* sBp = sAp + 3 * STGW;                            // 2 stages
    float* shb = reinterpret_cast<float*>(sBp + 2 * STGW);     // [512]
    float* sws = shb + 512;                                    // [512]
    float* srow = sws + 512;                                   // [128]

    const int tid = threadIdx.x, wid = tid >> 5, lane = tid & 31;
    const int wm = wid & 1, wn = wid >> 1;
    const int g = lane >> 2, tg = lane & 3;
    const int R0 = blockIdx.x * 128;
    const int jh = blockIdx.y;            // j-half: 0 or 1
    const int bidx = blockIdx.x >> 4;

    if (tid < 128) srow[tid] = 0.f;

    // prologue: convert own block fp32 -> fp16 (both j-halves write identical
    // bytes - benign); fill this half's shb/sws tables
    {
        const float* aF = enc + (size_t)R0 * ENCD;
        __half* aHw = g_encH + (size_t)R0 * ENCD;
#pragma unroll 4
        for (int i = tid; i < 128 * ENCD / 8; i += 256) {
            size_t off = (size_t)i * 8;
            float4 v0 = *reinterpret_cast<const float4*>(aF + off);
            float4 v1 = *reinterpret_cast<const float4*>(aF + off + 4);
            __half2 h[4];
            h[0] = __floats2half2_rn(v0.x, v0.y);
            h[1] = __floats2half2_rn(v0.z, v0.w);
            h[2] = __floats2half2_rn(v1.x, v1.y);
            h[3] = __floats2half2_rn(v1.z, v1.w);
            *reinterpret_cast<uint4*>(aHw + off) = *reinterpret_cast<uint4*>(h);
        }
#pragma unroll
        for (int i = tid; i < 512; i += 256) {
            int j = jh * 512 + i;
            shb[i] = g_h[bidx * UU + j] + bc[j];
            sws[i] = Ws[j];
        }
        __threadfence();
        __syncthreads();
    }

    const uint32_t sA0 = smem_u32(sAp);
    const uint32_t sB0 = smem_u32(sBp);
    const __half* aBase = g_encH + (size_t)R0 * ENCD;

    uint32_t aOff[4], bOff[2];
#pragma unroll
    for (int mt = 0; mt < 4; mt++) {
        int row = wm * 64 + mt * 16 + ((lane >> 3) & 1) * 8 + (lane & 7);
        aOff[mt] = (row * SKW + ((lane >> 4) << 2)) * 4;
    }
#pragma unroll
    for (int np = 0; np < 2; np++) {
        int row = wn * 32 + np * 16 + ((lane >> 4) & 1) * 8 + (lane & 7);
        bOff[np] = (row * SKW + (((lane >> 3) & 1) << 2)) * 4;
    }

    // loaders: A stage = it % 3, B stage = it & 1
    auto load_A = [&](int it, int sa) {
        int kc = it & 15;
        const __half* aSrc = aBase + kc * 64;
        uint32_t aDst = sA0 + sa * STGB;
#pragma unroll
        for (int i = 0; i < 4; i++) {
            int idx = tid + i * 256;
            int row = idx >> 3, seg = idx & 7;
            cp16(aDst + (row * SKW + seg * 4) * 4, aSrc + (size_t)row * ENCD + seg * 8);
        }
    };
    auto load_B = [&](int it) {
        int kc = it & 15, jt = jh * 4 + (it >> 4);
        const __half* bSrc = g_WcTH + (size_t)(jt * 128) * ENCD + kc * 64;
        uint32_t bDst = sB0 + (it & 1) * STGB;
#pragma unroll
        for (int i = 0; i < 4; i++) {
            int idx = tid + i * 256;
            int row = idx >> 3, seg = idx & 7;
            cp16(bDst + (row * SKW + seg * 4) * 4, bSrc + (size_t)row * ENCD + seg * 8);
        }
    };

    float c[4][4][4];
#pragma unroll
    for (int a = 0; a < 4; a++)
#pragma unroll
        for (int b2 = 0; b2 < 4; b2++)
#pragma unroll
            for (int d = 0; d < 4; d++) c[a][b2][d] = 0.f;
    float rowacc[4][2] = {{0.f, 0.f}, {0.f, 0.f}, {0.f, 0.f}, {0.f, 0.f}};

    // prologue groups (FIFO): [B0][A0][A1]
    load_B(0); CP_COMMIT();
    load_A(0, 0); CP_COMMIT();
    load_A(1, 1); CP_COMMIT();

    const int TOT = 64;
    int sa = 0;                   // it % 3
    int sa2 = 2;                  // (it+2) % 3
    for (int it = 0; it < TOT; it++) {
        const int kc = it & 15;
        // pending (oldest->newest): A(it), B(it), A(it+1) -> drain first two
        if (it == TOT - 1) { CP_WAIT0(); } else { CP_WAIT1(); }
        __syncthreads();

        if (it + 1 < TOT) { load_B(it + 1); CP_COMMIT(); }
        if (it + 2 < TOT) { load_A(it + 2, sa2); CP_COMMIT(); }

        const uint32_t aB = sA0 + sa * STGB;
        const uint32_t bB = sB0 + (it & 1) * STGB;
#pragma unroll
        for (int ks = 0; ks < 4; ks++) {
            uint32_t bf[4][2];
#pragma unroll
            for (int np = 0; np < 2; np++)
                LDSM4(bf[2 * np][0], bf[2 * np][1], bf[2 * np + 1][0], bf[2 * np + 1][1],
                      bB + bOff[np] + ks * 32);
#pragma unroll
            for (int mt = 0; mt < 4; mt++) {
                uint32_t af[4];
                LDSM4(af[0], af[1], af[2], af[3], aB + aOff[mt] + ks * 32);
#pragma unroll
                for (int nt = 0; nt < 4; nt++) MMA_F16(c[mt][nt], af, bf[nt]);
            }
        }

        if (kc == 15) {
            const int jtl = it >> 4;
            const float* hb8 = shb + jtl * 128;
            const float* ws8 = sws + jtl * 128;
#pragma unroll
            for (int mt = 0; mt < 4; mt++) {
                float rs0 = 0.f, rs1 = 0.f;
#pragma unroll
                for (int nt = 0; nt < 4; nt++) {
                    int nl = wn * 32 + nt * 8 + tg * 2;
#pragma unroll
                    for (int cc = 0; cc < 2; cc++) {
                        float hb = hb8[nl + cc], ws = ws8[nl + cc];
                        rs0 += htanh(c[mt][nt][cc] + hb) * ws;
                        rs1 += htanh(c[mt][nt][2 + cc] + hb) * ws;
                    }
                }
                rs0 += __shfl_xor_sync(0xffffffffu, rs0, 1);
                rs0 += __shfl_xor_sync(0xffffffffu, rs0, 2);
                rs1 += __shfl_xor_sync(0xffffffffu, rs1, 1);
                rs1 += __shfl_xor_sync(0xffffffffu, rs1, 2);
                rowacc[mt][0] += rs0;
                rowacc[mt][1] += rs1;
#pragma unroll
                for (int nt = 0; nt < 4; nt++)
#pragma unroll
                    for (int d = 0; d < 4; d++) c[mt][nt][d] = 0.f;
            }
        }

        sa = (sa == 2) ? 0 : sa + 1;
        sa2 = (sa2 == 2) ? 0 : sa2 + 1;
    }

#pragma unroll
    for (int mt = 0; mt < 4; mt++) {
        if (tg == 0) {
            atomicAdd(&srow[wm * 64 + mt * 16 + g], rowacc[mt][0]);
            atomicAdd(&srow[wm * 64 + mt * 16 + 8 + g], rowacc[mt][1]);
        }
    }
    __syncthreads();
    if (tid < 128) g_s[jh * MROWS + R0 + tid] = srow[tid];
}

// ---------------- k_softmax : sums the two j-half partials -------------------
__global__ void k_softmax(const float* __restrict__ bs) {
    __shared__ float sv[SRC];
    __shared__ float red[256];
    int b = blockIdx.x, tid = threadIdx.x;
    float bsv = bs[0];
    float lmax = -1e30f;
    for (int t = tid; t < SRC; t += 256) {
        float s = bsv + g_s[b * SRC + t] + g_s[MROWS + b * SRC + t];
        sv[t] = s;
        lmax = fmaxf(lmax, s);
    }
    red[tid] = lmax;
    __syncthreads();
    for (int off = 128; off; off >>= 1) {
        if (tid < off) red[tid] = fmaxf(red[tid], red[tid + off]);
        __syncthreads();
    }
    float m = red[0];
    __syncthreads();
    float lsum = 0.f;
    for (int t = tid; t < SRC; t += 256) {
        float e = expf(sv[t] - m);
        sv[t] = e;
        lsum += e;
    }
    red[tid] = lsum;
    __syncthreads();
    for (int off = 128; off; off >>= 1) {
        if (tid < off) red[tid] += red[tid + off];
        __syncthreads();
    }
    float inv = 1.f / red[0];
    for (int t = tid; t < SRC; t += 256) g_w[b * SRC + t] = sv[t] * inv;
}

// ---------------- k_ctx : 16-way segmented weighted sum, half2 loads ---------
// grid: (ENCD/512, BB, 16); t-block = 128
__global__ void k_ctx() {
    __shared__ float sw[128];
    int b = blockIdx.y, seg = blockIdx.z;
    int k2 = blockIdx.x * 256 + threadIdx.x;     // half2 column index
    int t0 = seg * 128;
    if (threadIdx.x < 128) sw[threadIdx.x] = g_w[b * SRC + t0 + threadIdx.x];
    __syncthreads();
    const __half2* ep = reinterpret_cast<const __half2*>(
                            g_encH + ((size_t)b * SRC + t0) * ENCD) + k2;
    float ax0 = 0.f, ay0 = 0.f, ax1 = 0.f, ay1 = 0.f;
    float ax2 = 0.f, ay2 = 0.f, ax3 = 0.f, ay3 = 0.f;
    for (int t = 0; t < 128; t += 8) {
#pragma unroll
        for (int u = 0; u < 8; u += 4) {
            float2 v0 = __half22float2(ep[(size_t)(t + u) * (ENCD / 2)]);
            float2 v1 = __half22float2(ep[(size_t)(t + u + 1) * (ENCD / 2)]);
            float2 v2 = __half22float2(ep[(size_t)(t + u + 2) * (ENCD / 2)]);
            float2 v3 = __half22float2(ep[(size_t)(t + u + 3) * (ENCD / 2)]);
            float w0 = sw[t + u], w1 = sw[t + u + 1];
            float w2 = sw[t + u + 2], w3 = sw[t + u + 3];
            ax0 += w0 * v0.x; ay0 += w0 * v0.y;
            ax1 += w1 * v1.x; ay1 += w1 * v1.y;
            ax2 += w2 * v2.x; ay2 += w2 * v2.y;
            ax3 += w3 * v3.x; ay3 += w3 * v3.y;
        }
    }
    g_ctxp[seg][b][2 * k2] = (ax0 + ax1) + (ax2 + ax3);
    g_ctxp[seg][b][2 * k2 + 1] = (ay0 + ay1) + (ay2 + ay3);
}

// ---------------- k_xin : xin = concat(sum(ctx partials), emb[x]), float4 ----
__global__ void k_xin(const int* __restrict__ x, const float* __restrict__ emb) {
    int b = blockIdx.x;
    int xi = x[b];
    for (int i4 = threadIdx.x; i4 < IN0 / 4; i4 += 256) {
        float4 v;
        if (i4 < ENCD / 4) {
            v = make_float4(0.f, 0.f, 0.f, 0.f);
#pragma unroll
            for (int seg = 0; seg < 16; seg++) {
                float4 p = *reinterpret_cast<const float4*>(&g_ctxp[seg][b][i4 * 4]);
                v.x += p.x; v.y += p.y; v.z += p.z; v.w += p.w;
            }
        } else {
            v = *reinterpret_cast<const float4*>(
                    emb + (size_t)xi * EE + (i4 * 4 - ENCD));
        }
        *reinterpret_cast<float4*>(&g_xin[b * IN0 + i4 * 4]) = v;
    }
}

// ---------------- tf32 GEMM body, 4-stage cp.async, cvt-in-fragment ---------
#define GA_W (64 * 36)
#define GB_W (32 * 132)
#define GB_SMEM (4 * (GA_W + GB_W) * 4)

template <int EPI>
__device__ __forceinline__ void gemm_body(const float* __restrict__ A,
                                          const float* __restrict__ B,
                                          const float* __restrict__ bias,
                                          float* __restrict__ C,
                                          int lda, int Kloop, int N, int col0) {
    extern __shared__ float gsm[];
    float* sA4 = gsm;                 // 4 x GA_W
    float* sB4 = gsm + 4 * GA_W;      // 4 x GB_W
    const int tid = threadIdx.x;
    const int wid = tid >> 5, lane = tid & 31;
    const int wm = wid & 1, wn = wid >> 1;
    const int g = lane >> 2, tg = lane & 3;

    const uint32_t a0 = smem_u32(sA4);
    const uint32_t b0 = smem_u32(sB4);

    auto load_kc = [&](int kc) {
        int s = kc & 3;
        int k0 = kc * 32;
        uint32_t aDst = a0 + s * (GA_W * 4);
        uint32_t bDst = b0 + s * (GB_W * 4);
#pragma unroll
        for (int i = 0; i < 2; i++) {
            int idx = tid + i * 256;
            int row = idx >> 3, seg = idx & 7;
            cp16(aDst + (row * 36 + seg * 4) * 4, A + (size_t)row * lda + k0 + seg * 4);
        }
#pragma unroll
        for (int i = 0; i < 4; i++) {
            int idx = tid + i * 256;
            int rb = idx >> 5, c4 = idx & 31;
            cp16(bDst + (rb * 132 + c4 * 4) * 4, B + (size_t)(k0 + rb) * N + col0 + c4 * 4);
        }
    };

    float c[2][4][4];
#pragma unroll
    for (int a = 0; a < 2; a++)
#pragma unroll
        for (int b2 = 0; b2 < 4; b2++)
#pragma unroll
            for (int d = 0; d < 4; d++) c[a][b2][d] = 0.f;

    const int NK = Kloop / 32;
    load_kc(0); CP_COMMIT();
    if (NK > 1) load_kc(1);
    CP_COMMIT();
    if (NK > 2) load_kc(2);
    CP_COMMIT();

    for (int kc = 0; kc < NK; kc++) {
        int s = kc & 3;
        CP_WAIT2();                 // 3 groups in flight; drain oldest (kc)
        __syncthreads();
        if (kc + 3 < NK) load_kc(kc + 3);
        CP_COMMIT();                // keep 3 groups pending

        const float* pA = sA4 + s * GA_W;
        const float* pB = sB4 + s * GB_W;
#pragma unroll
        for (int ks = 0; ks < 4; ks++) {
            const int kb = ks * 8;
            unsigned af[2][4], bf[4][2];
#pragma unroll
            for (int mt = 0; mt < 2; mt++) {
                int r = wm * 32 + mt * 16 + g;
                af[mt][0] = f2tf32(pA[r * 36 + kb + tg]);
                af[mt][1] = f2tf32(pA[(r + 8) * 36 + kb + tg]);
                af[mt][2] = f2tf32(pA[r * 36 + kb + tg + 4]);
                af[mt][3] = f2tf32(pA[(r + 8) * 36 + kb + tg + 4]);
            }
#pragma unroll
            for (int nt = 0; nt < 4; nt++) {
                int col = wn * 32 + nt * 8 + g;
                bf[nt][0] = f2tf32(pB[(kb + tg) * 132 + col]);
                bf[nt][1] = f2tf32(pB[(kb + tg + 4) * 132 + col]);
            }
#pragma unroll
            for (int mt = 0; mt < 2; mt++)
#pragma unroll
                for (int nt = 0; nt < 4; nt++) MMA_TF32(c[mt][nt], af[mt], bf[nt]);
        }
    }
#pragma unroll
    for (int mt = 0; mt < 2; mt++)
#pragma unroll
        for (int nt = 0; nt < 4; nt++) {
            int r = wm * 32 + mt * 16 + g;
            int col = col0 + wn * 32 + nt * 8 + tg * 2;
            float add0 = 0.f, add1 = 0.f;
            if (EPI == 1) { add0 = bias[col]; add1 = bias[col + 1]; }
            C[(size_t)r * N + col] = c[mt][nt][0] + add0;
            C[(size_t)r * N + col + 1] = c[mt][nt][1] + add1;
            C[(size_t)(r + 8) * N + col] = c[mt][nt][2] + add0;
            C[(size_t)(r + 8) * N + col + 1] = c[mt][nt][3] + add1;
        }
}

template <int EPI>
__global__ __launch_bounds__(256, 2) void k_gemm(const float* __restrict__ A,
                                                 const float* __restrict__ B,
                                                 const float* __restrict__ bias,
                                                 float* __restrict__ C, int K, int N) {
    gemm_body<EPI>(A, B, bias, C, K, K, N, blockIdx.x * 128);
}

// split-K paired GEMM: grid (N/128, 2 pairs, NSPLIT splits)
__global__ __launch_bounds__(256, 2) void k_gemm_splitk(
    const float* A0, const float* A1, const float* B0, const float* B1,
    float* Cp, int K, int N) {
    const int pair = blockIdx.y, z = blockIdx.z;
    const float* A = pair ? A1 : A0;
    const float* B = pair ? B1 : B0;
    const int Ks = K / NSPLIT;
    float* C = Cp + ((size_t)z * 2 + pair) * XSEG;
    gemm_body<0>(A + z * Ks, B + (size_t)z * Ks * N, nullptr, C,
                 K, Ks, N, blockIdx.x * 128);
}

// ---------------- k_gru_pair : sums NSPLIT split-K partials + pointwise GRU --
// float4 over u: 256 threads x 4 = 1024 = UU
__global__ void k_gru_pair(const float* xgp, const float* b0v, const float* b1v,
                           float* o0, float* o1, float* y0, float* y1) {
    const int pair = blockIdx.y;
    const float* xg = xgp + (size_t)pair * XSEG;
    const float* bvec = pair ? b1v : b0v;
    float* hout = pair ? o1 : o0;
    float* yout = pair ? y1 : y0;
    int b = blockIdx.x;
    const size_t ZS = 2 * (size_t)XSEG;
    int u = threadIdx.x * 4;
    size_t iz = (size_t)b * 3 * UU + u;
    size_t ir = iz + UU, ih = iz + 2 * UU;

    float4 xz = make_float4(0.f, 0.f, 0.f, 0.f);
    float4 xr = xz, xh = xz;
#pragma unroll
    for (int z = 0; z < NSPLIT; z++) {
        float4 pz = *reinterpret_cast<const float4*>(xg + iz + z * ZS);
        float4 pr = *reinterpret_cast<const float4*>(xg + ir + z * ZS);
        float4 ph = *reinterpret_cast<const float4*>(xg + ih + z * ZS);
        xz.x += pz.x; xz.y += pz.y; xz.z += pz.z; xz.w += pz.w;
        xr.x += pr.x; xr.y += pr.y; xr.z += pr.z; xr.w += pr.w;
        xh.x += ph.x; xh.y += ph.y; xh.z += ph.z; xh.w += ph.w;
    }
    float4 b0z = *reinterpret_cast<const float4*>(bvec + u);
    float4 b0r = *reinterpret_cast<const float4*>(bvec + UU + u);
    float4 b0h = *reinterpret_cast<const float4*>(bvec + 2 * UU + u);
    float4 b1z = *reinterpret_cast<const float4*>(bvec + 3 * UU + u);
    float4 b1r = *reinterpret_cast<const float4*>(bvec + 3 * UU + UU + u);
    float4 b1h = *reinterpret_cast<const float4*>(bvec + 3 * UU + 2 * UU + u);

    float4 hres;
    {
        float vz[4] = {xz.x + b0z.x + b1z.x, xz.y + b0z.y + b1z.y,
                       xz.z + b0z.z + b1z.z, xz.w + b0z.w + b1z.w};
        float vr[4] = {xr.x + b0r.x + b1r.x, xr.y + b0r.y + b1r.y,
                       xr.z + b0r.z + b1r.z, xr.w + b0r.w + b1r.w};
        float vh[4] = {xh.x + b0h.x, xh.y + b0h.y, xh.z + b0h.z, xh.w + b0h.w};
        float v1h[4] = {b1h.x, b1h.y, b1h.z, b1h.w};
        float* hr = reinterpret_cast<float*>(&hres);
#pragma unroll
        for (int q = 0; q < 4; q++) {
            float z = 1.f / (1.f + expf(-vz[q]));
            float r = 1.f / (1.f + expf(-vr[q]));
            float hc = tanhf(vh[q] + r * v1h[q]);
            hr[q] = (1.f - z) * hc;
        }
    }
    *reinterpret_cast<float4*>(hout + b * UU + u) = hres;
    if (yout) *reinterpret_cast<float4*>(yout + b * 2 * UU + u) = hres;
}

// ---------------- host launcher ----------------------------------------------
extern "C" void kernel_launch(void* const* d_in, const int* in_sizes, int n_in,
                              void* d_out, int out_size) {
    (void)in_sizes; (void)n_in; (void)out_size;
    const int* x = (const int*)d_in[0];
    const float* state = (const float*)d_in[1];
    const float* enc = (const float*)d_in[2];
    const float* Wh = (const float*)d_in[3];
    const float* bh = (const float*)d_in[4];
    const float* Wc = (const float*)d_in[5];
    const float* bc = (const float*)d_in[6];
    const float* Ws = (const float*)d_in[7];
    const float* bs = (const float*)d_in[8];
    const float* emb = (const float*)d_in[9];
    const float* fw0_k = (const float*)d_in[10];
    const float* fw0_b = (const float*)d_in[12];
    const float* fw1_k = (const float*)d_in[13];
    const float* fw1_b = (const float*)d_in[15];
    const float* bw0_k = (const float*)d_in[16];
    const float* bw0_b = (const float*)d_in[18];
    const float* bw1_k = (const float*)d_in[19];
    const float* bw1_b = (const float*)d_in[21];
    const float* fcW = (const float*)d_in[22];
    const float* fcb = (const float*)d_in[23];

    float* out = (float*)d_out;
    float* h0f = out + (size_t)BB * VV;
    float* h1f = h0f + BB * UU;
    float* h0b = h1f + BB * UU;
    float* h1b = h0b + BB * UU;

    float *p_xin, *p_xgp, *p_y;
    cudaGetSymbolAddress((void**)&p_xin, g_xin);
    cudaGetSymbolAddress((void**)&p_xgp, g_xgp);
    cudaGetSymbolAddress((void**)&p_y, g_y);

    cudaFuncSetAttribute(k_score, cudaFuncAttributeMaxDynamicSharedMemorySize, SC_SMEM);
    cudaFuncSetAttribute(k_gemm<1>, cudaFuncAttributeMaxDynamicSharedMemorySize, GB_SMEM);
    cudaFuncSetAttribute(k_gemm_splitk, cudaFuncAttributeMaxDynamicSharedMemorySize, GB_SMEM);

    // attention
    k_prep<<<PREP_TOTAL, 256>>>(Wc, state, Wh, bh);
    k_score<<<dim3(MROWS / 128, 2), 256, SC_SMEM>>>(enc, bc, Ws);
    k_softmax<<<BB, 256>>>(bs);
    k_ctx<<<dim3(ENCD / 512, BB, 16), 256>>>();
    k_xin<<<BB, 256>>>(x, emb);

    // GRU stacks (zero hidden state => rk unused); fw/bw paired, split-K x8
    k_gemm_splitk<<<dim3(3 * UU / 128, 2, NSPLIT), 256, GB_SMEM>>>(
        p_xin, p_xin, fw0_k, bw0_k, p_xgp, IN0, 3 * UU);
    k_gru_pair<<<dim3(BB, 2), 256>>>(p_xgp, fw0_b, bw0_b, h0f, h0b, nullptr, nullptr);
    k_gemm_splitk<<<dim3(3 * UU / 128, 2, NSPLIT), 256, GB_SMEM>>>(
        h0f, h0b, fw1_k, bw1_k, p_xgp, UU, 3 * UU);
    k_gru_pair<<<dim3(BB, 2), 256>>>(p_xgp, fw1_b, bw1_b, h1f, h1b,
                                     p_y, p_y + UU);

    // output projection
    k_gemm<1><<<dim3(VV / 128, 1), 256, GB_SMEM>>>(p_y, fcW, fcb, out, 2 * UU, VV);
}

// round 15
// speedup vs baseline: 1.0382x; 1.0382x over previous
#include <cuda_runtime.h>
#include <cuda_fp16.h>
#include <cstdint>

// Problem constants
#define BB   64
#define SRC  2048
#define ENCD 1024
#define UU   1024
#define EE   512
#define VV   32000
#define IN0  (ENCD + EE)        // 1536
#define MROWS (BB * SRC)        // 131072
#define XSEG (BB * 3 * UU)      // one gate-preact buffer
#define NSPLIT 8
#define NSEG 32

// ---------------- scratch (device globals; no allocation allowed) -----------
__device__ float  g_h[BB * UU];
__device__ __half g_encH[(size_t)MROWS * ENCD];   // enc in fp16 (256MB)
__device__ __half g_WcTH[ENCD * UU];              // Wc transposed fp16
__device__ float  g_s[MROWS];                     // scores
__device__ float  g_w[BB * SRC];                  // softmax weights
__device__ float  g_ctxp[NSEG][BB][ENCD];
__device__ float  g_xin[BB * IN0];
__device__ float  g_xgp[NSPLIT][2][XSEG];         // split-K partials
__device__ float  g_y[BB * 2 * UU];

// ---------------- helpers ----------------------------------------------------
__device__ __forceinline__ unsigned f2tf32(float f) {
    unsigned u;
    asm("cvt.rna.tf32.f32 %0, %1;" : "=r"(u) : "f"(f));
    return u;
}
__device__ __forceinline__ float htanh(float x) {
    float r;
    asm("tanh.approx.f32 %0, %1;" : "=f"(r) : "f"(x));
    return r;
}
__device__ __forceinline__ uint32_t smem_u32(const void* p) {
    uint32_t a;
    asm("{ .reg .u64 t; cvta.to.shared.u64 t, %1; cvt.u32.u64 %0, t; }" : "=r"(a) : "l"(p));
    return a;
}
__device__ __forceinline__ void cp16(uint32_t dst, const void* src) {
    asm volatile("cp.async.cg.shared.global [%0], [%1], 16;\n" :: "r"(dst), "l"(src));
}
#define CP_COMMIT() asm volatile("cp.async.commit_group;" ::: "memory")
#define CP_WAIT0()  asm volatile("cp.async.wait_group 0;" ::: "memory")
#define CP_WAIT1()  asm volatile("cp.async.wait_group 1;" ::: "memory")
#define CP_WAIT2()  asm volatile("cp.async.wait_group 2;" ::: "memory")

#define LDSM4(r0, r1, r2, r3, addr)                                              \
    asm volatile("ldmatrix.sync.aligned.m8n8.x4.shared.b16 {%0,%1,%2,%3}, [%4];" \
                 : "=r"(r0), "=r"(r1), "=r"(r2), "=r"(r3) : "r"(addr))

// fp16 mma m16n8k16 with fp32 accumulate
#define MMA_F16(c, a, b)                                                         \
    asm volatile(                                                                \
        "mma.sync.aligned.m16n8k16.row.col.f32.f16.f16.f32 "                     \
        "{%0,%1,%2,%3},{%4,%5,%6,%7},{%8,%9},{%0,%1,%2,%3};\n"                   \
        : "+f"((c)[0]), "+f"((c)[1]), "+f"((c)[2]), "+f"((c)[3])                 \
        : "r"((a)[0]), "r"((a)[1]), "r"((a)[2]), "r"((a)[3]),                    \
          "r"((b)[0]), "r"((b)[1]))

// tf32 mma m16n8k8 (small GEMMs)
#define MMA_TF32(c, a, b)                                                        \
    asm volatile(                                                                \
        "mma.sync.aligned.m16n8k8.row.col.f32.tf32.tf32.f32 "                    \
        "{%0,%1,%2,%3},{%4,%5,%6,%7},{%8,%9},{%0,%1,%2,%3};\n"                   \
        : "+f"((c)[0]), "+f"((c)[1]), "+f"((c)[2]), "+f"((c)[3])                 \
        : "r"((a)[0]), "r"((a)[1]), "r"((a)[2]), "r"((a)[3]),                    \
          "r"((b)[0]), "r"((b)[1]))

// ---------------- k_prep : Wc transpose | h = state@Wh+bh (4-way col split) --
#define PREP_TR_BLKS 1024
#define PREP_TOTAL (PREP_TR_BLKS + BB * 4)

__global__ void k_prep(const float* __restrict__ Wc,
                       const float* __restrict__ state, const float* __restrict__ Wh,
                       const float* __restrict__ bh) {
    __shared__ float sbuf[32 * 33];
    const int bx = blockIdx.x, tid = threadIdx.x;

    if (bx < PREP_TR_BLKS) {
        int j0 = (bx & 31) * 32, k0 = (bx >> 5) * 32;
        int lx = tid & 31, ly = tid >> 5;
        float (*t)[33] = reinterpret_cast<float(*)[33]>(sbuf);
#pragma unroll
        for (int i = 0; i < 4; i++) {
            int kk = ly + i * 8;
            t[kk][lx] = Wc[(size_t)(k0 + kk) * UU + j0 + lx];
        }
        __syncthreads();
#pragma unroll
        for (int i = 0; i < 4; i++) {
            int jj = ly + i * 8;
            g_WcTH[(size_t)(j0 + jj) * ENCD + k0 + lx] = __float2half_rn(t[lx][jj]);
        }
    } else {
        int idx = bx - PREP_TR_BLKS;
        int b = idx >> 2, jq = idx & 3;
        float* ss = sbuf;
        for (int i = tid; i < UU; i += 256) ss[i] = state[b * UU + i];
        __syncthreads();
        int col = jq * 256 + tid;
        float a0 = 0.f, a1 = 0.f, a2 = 0.f, a3 = 0.f;
#pragma unroll 2
        for (int k = 0; k < UU; k += 4) {
            a0 += ss[k] * Wh[(size_t)k * UU + col];
            a1 += ss[k + 1] * Wh[(size_t)(k + 1) * UU + col];
            a2 += ss[k + 2] * Wh[(size_t)(k + 2) * UU + col];
            a3 += ss[k + 3] * Wh[(size_t)(k + 3) * UU + col];
        }
        g_h[b * UU + col] = (a0 + a1) + (a2 + a3) + bh[col];
    }
}

// ---------------- k_score : fp16 mma, BK=64, asymmetric 3A/2B staging -------
// (R9/R13 configuration: 256 threads, warp tile 64x32, occ 2, grid 1024)
#define SKW 36                   // smem row stride in words (32 data + 4 pad)
#define STGW (128 * SKW)
#define STGB (STGW * 4)          // 18432 bytes per stage
#define SC_SMEM ((3 + 2) * STGB + (1024 + 1024 + 128) * 4)

__global__ __launch_bounds__(256, 2) void k_score(const float* __restrict__ enc,
                                                  const float* __restrict__ bc,
                                                  const float* __restrict__ Ws) {
    extern __shared__ char dsm[];
    uint32_t* sAp = reinterpret_cast<uint32_t*>(dsm);          // 3 stages
    uint32_t* sBp = sAp + 3 * STGW;                            // 2 stages
    float* shb = reinterpret_cast<float*>(sBp + 2 * STGW);     // [1024]
    float* sws = shb + 1024;                                   // [1024]
    float* srow = sws + 1024;                                  // [128]

    const int tid = threadIdx.x, wid = tid >> 5, lane = tid & 31;
    const int wm = wid & 1, wn = wid >> 1;
    const int g = lane >> 2, tg = lane & 3;
    const int R0 = blockIdx.x * 128;
    const int bidx = blockIdx.x >> 4;

    if (tid < 128) srow[tid] = 0.f;

    // prologue: convert own block fp32 -> fp16; fill shb/sws tables
    {
        const float* aF = enc + (size_t)R0 * ENCD;
        __half* aHw = g_encH + (size_t)R0 * ENCD;
#pragma unroll 4
        for (int i = tid; i < 128 * ENCD / 8; i += 256) {
            size_t off = (size_t)i * 8;
            float4 v0 = *reinterpret_cast<const float4*>(aF + off);
            float4 v1 = *reinterpret_cast<const float4*>(aF + off + 4);
            __half2 h[4];
            h[0] = __floats2half2_rn(v0.x, v0.y);
            h[1] = __floats2half2_rn(v0.z, v0.w);
            h[2] = __floats2half2_rn(v1.x, v1.y);
            h[3] = __floats2half2_rn(v1.z, v1.w);
            *reinterpret_cast<uint4*>(aHw + off) = *reinterpret_cast<uint4*>(h);
        }
#pragma unroll
        for (int i = tid; i < 1024; i += 256) {
            shb[i] = g_h[bidx * UU + i] + bc[i];
            sws[i] = Ws[i];
        }
        __threadfence();
        __syncthreads();
    }

    const uint32_t sA0 = smem_u32(sAp);
    const uint32_t sB0 = smem_u32(sBp);
    const __half* aBase = g_encH + (size_t)R0 * ENCD;

    uint32_t aOff[4], bOff[2];
#pragma unroll
    for (int mt = 0; mt < 4; mt++) {
        int row = wm * 64 + mt * 16 + ((lane >> 3) & 1) * 8 + (lane & 7);
        aOff[mt] = (row * SKW + ((lane >> 4) << 2)) * 4;
    }
#pragma unroll
    for (int np = 0; np < 2; np++) {
        int row = wn * 32 + np * 16 + ((lane >> 4) & 1) * 8 + (lane & 7);
        bOff[np] = (row * SKW + (((lane >> 3) & 1) << 2)) * 4;
    }

    // loaders: A stage = it % 3, B stage = it & 1
    auto load_A = [&](int it, int sa) {
        int kc = it & 15;
        const __half* aSrc = aBase + kc * 64;
        uint32_t aDst = sA0 + sa * STGB;
#pragma unroll
        for (int i = 0; i < 4; i++) {
            int idx = tid + i * 256;
            int row = idx >> 3, seg = idx & 7;
            cp16(aDst + (row * SKW + seg * 4) * 4, aSrc + (size_t)row * ENCD + seg * 8);
        }
    };
    auto load_B = [&](int it) {
        int kc = it & 15, jt = it >> 4;
        const __half* bSrc = g_WcTH + (size_t)(jt * 128) * ENCD + kc * 64;
        uint32_t bDst = sB0 + (it & 1) * STGB;
#pragma unroll
        for (int i = 0; i < 4; i++) {
            int idx = tid + i * 256;
            int row = idx >> 3, seg = idx & 7;
            cp16(bDst + (row * SKW + seg * 4) * 4, bSrc + (size_t)row * ENCD + seg * 8);
        }
    };

    float c[4][4][4];
#pragma unroll
    for (int a = 0; a < 4; a++)
#pragma unroll
        for (int b2 = 0; b2 < 4; b2++)
#pragma unroll
            for (int d = 0; d < 4; d++) c[a][b2][d] = 0.f;
    float rowacc[4][2] = {{0.f, 0.f}, {0.f, 0.f}, {0.f, 0.f}, {0.f, 0.f}};

    // prologue groups (FIFO): [B0][A0][A1]
    load_B(0); CP_COMMIT();
    load_A(0, 0); CP_COMMIT();
    load_A(1, 1); CP_COMMIT();

    const int TOT = 128;
    int sa = 0;                   // it % 3
    int sa2 = 2;                  // (it+2) % 3
    for (int it = 0; it < TOT; it++) {
        const int kc = it & 15;
        // pending (oldest->newest): A(it), B(it), A(it+1) -> drain first two
        if (it == TOT - 1) { CP_WAIT0(); } else { CP_WAIT1(); }
        __syncthreads();

        if (it + 1 < TOT) { load_B(it + 1); CP_COMMIT(); }
        if (it + 2 < TOT) { load_A(it + 2, sa2); CP_COMMIT(); }

        const uint32_t aB = sA0 + sa * STGB;
        const uint32_t bB = sB0 + (it & 1) * STGB;
#pragma unroll
        for (int ks = 0; ks < 4; ks++) {
            uint32_t bf[4][2];
#pragma unroll
            for (int np = 0; np < 2; np++)
                LDSM4(bf[2 * np][0], bf[2 * np][1], bf[2 * np + 1][0], bf[2 * np + 1][1],
                      bB + bOff[np] + ks * 32);
#pragma unroll
            for (int mt = 0; mt < 4; mt++) {
                uint32_t af[4];
                LDSM4(af[0], af[1], af[2], af[3], aB + aOff[mt] + ks * 32);
#pragma unroll
                for (int nt = 0; nt < 4; nt++) MMA_F16(c[mt][nt], af, bf[nt]);
            }
        }

        if (kc == 15) {
            const int jt = it >> 4;
            const float* hb8 = shb + jt * 128;
            const float* ws8 = sws + jt * 128;
#pragma unroll
            for (int mt = 0; mt < 4; mt++) {
                float rs0 = 0.f, rs1 = 0.f;
#pragma unroll
                for (int nt = 0; nt < 4; nt++) {
                    int nl = wn * 32 + nt * 8 + tg * 2;
#pragma unroll
                    for (int cc = 0; cc < 2; cc++) {
                        float hb = hb8[nl + cc], ws = ws8[nl + cc];
                        rs0 += htanh(c[mt][nt][cc] + hb) * ws;
                        rs1 += htanh(c[mt][nt][2 + cc] + hb) * ws;
                    }
                }
                rs0 += __shfl_xor_sync(0xffffffffu, rs0, 1);
                rs0 += __shfl_xor_sync(0xffffffffu, rs0, 2);
                rs1 += __shfl_xor_sync(0xffffffffu, rs1, 1);
                rs1 += __shfl_xor_sync(0xffffffffu, rs1, 2);
                rowacc[mt][0] += rs0;
                rowacc[mt][1] += rs1;
#pragma unroll
                for (int nt = 0; nt < 4; nt++)
#pragma unroll
                    for (int d = 0; d < 4; d++) c[mt][nt][d] = 0.f;
            }
        }

        sa = (sa == 2) ? 0 : sa + 1;
        sa2 = (sa2 == 2) ? 0 : sa2 + 1;
    }

#pragma unroll
    for (int mt = 0; mt < 4; mt++) {
        if (tg == 0) {
            atomicAdd(&srow[wm * 64 + mt * 16 + g], rowacc[mt][0]);
            atomicAdd(&srow[wm * 64 + mt * 16 + 8 + g], rowacc[mt][1]);
        }
    }
    __syncthreads();
    if (tid < 128) g_s[R0 + tid] = srow[tid];
}

// ---------------- k_softmax ---------------------------------------------------
__global__ void k_softmax(const float* __restrict__ bs) {
    __shared__ float sv[SRC];
    __shared__ float red[256];
    int b = blockIdx.x, tid = threadIdx.x;
    float bsv = bs[0];
    float lmax = -1e30f;
    for (int t = tid; t < SRC; t += 256) {
        float s = bsv + g_s[b * SRC + t];
        sv[t] = s;
        lmax = fmaxf(lmax, s);
    }
    red[tid] = lmax;
    __syncthreads();
    for (int off = 128; off; off >>= 1) {
        if (tid < off) red[tid] = fmaxf(red[tid], red[tid + off]);
        __syncthreads();
    }
    float m = red[0];
    __syncthreads();
    float lsum = 0.f;
    for (int t = tid; t < SRC; t += 256) {
        float e = expf(sv[t] - m);
        sv[t] = e;
        lsum += e;
    }
    red[tid] = lsum;
    __syncthreads();
    for (int off = 128; off; off >>= 1) {
        if (tid < off) red[tid] += red[tid + off];
        __syncthreads();
    }
    float inv = 1.f / red[0];
    for (int t = tid; t < SRC; t += 256) g_w[b * SRC + t] = sv[t] * inv;
}

// ---------------- k_ctx : 32-way segmented weighted sum, half2 loads ---------
// grid: (ENCD/512, BB, 32); t-chunk = 64
__global__ void k_ctx() {
    __shared__ float sw[64];
    int b = blockIdx.y, seg = blockIdx.z;
    int k2 = blockIdx.x * 256 + threadIdx.x;     // half2 column index
    int t0 = seg * 64;
    if (threadIdx.x < 64) sw[threadIdx.x] = g_w[b * SRC + t0 + threadIdx.x];
    __syncthreads();
    const __half2* ep = reinterpret_cast<const __half2*>(
                            g_encH + ((size_t)b * SRC + t0) * ENCD) + k2;
    float ax0 = 0.f, ay0 = 0.f, ax1 = 0.f, ay1 = 0.f;
    float ax2 = 0.f, ay2 = 0.f, ax3 = 0.f, ay3 = 0.f;
    for (int t = 0; t < 64; t += 8) {
#pragma unroll
        for (int u = 0; u < 8; u += 4) {
            float2 v0 = __half22float2(ep[(size_t)(t + u) * (ENCD / 2)]);
            float2 v1 = __half22float2(ep[(size_t)(t + u + 1) * (ENCD / 2)]);
            float2 v2 = __half22float2(ep[(size_t)(t + u + 2) * (ENCD / 2)]);
            float2 v3 = __half22float2(ep[(size_t)(t + u + 3) * (ENCD / 2)]);
            float w0 = sw[t + u], w1 = sw[t + u + 1];
            float w2 = sw[t + u + 2], w3 = sw[t + u + 3];
            ax0 += w0 * v0.x; ay0 += w0 * v0.y;
            ax1 += w1 * v1.x; ay1 += w1 * v1.y;
            ax2 += w2 * v2.x; ay2 += w2 * v2.y;
            ax3 += w3 * v3.x; ay3 += w3 * v3.y;
        }
    }
    g_ctxp[seg][b][2 * k2] = (ax0 + ax1) + (ax2 + ax3);
    g_ctxp[seg][b][2 * k2 + 1] = (ay0 + ay1) + (ay2 + ay3);
}

// ---------------- k_xin : xin = concat(sum(ctx partials), emb[x]), float4 ----
__global__ void k_xin(const int* __restrict__ x, const float* __restrict__ emb) {
    int b = blockIdx.x;
    int xi = x[b];
    for (int i4 = threadIdx.x; i4 < IN0 / 4; i4 += 256) {
        float4 v;
        if (i4 < ENCD / 4) {
            v = make_float4(0.f, 0.f, 0.f, 0.f);
#pragma unroll
            for (int seg = 0; seg < NSEG; seg++) {
                float4 p = *reinterpret_cast<const float4*>(&g_ctxp[seg][b][i4 * 4]);
                v.x += p.x; v.y += p.y; v.z += p.z; v.w += p.w;
            }
        } else {
            v = *reinterpret_cast<const float4*>(
                    emb + (size_t)xi * EE + (i4 * 4 - ENCD));
        }
        *reinterpret_cast<float4*>(&g_xin[b * IN0 + i4 * 4]) = v;
    }
}

// ---------------- tf32 GEMM body, 4-stage cp.async, cvt-in-fragment ---------
#define GA_W (64 * 36)
#define GB_W (32 * 132)
#define GB_SMEM (4 * (GA_W + GB_W) * 4)

template <int EPI>
__device__ __forceinline__ void gemm_body(const float* __restrict__ A,
                                          const float* __restrict__ B,
                                          const float* __restrict__ bias,
                                          float* __restrict__ C,
                                          int lda, int Kloop, int N, int col0) {
    extern __shared__ float gsm[];
    float* sA4 = gsm;                 // 4 x GA_W
    float* sB4 = gsm + 4 * GA_W;      // 4 x GB_W
    const int tid = threadIdx.x;
    const int wid = tid >> 5, lane = tid & 31;
    const int wm = wid & 1, wn = wid >> 1;
    const int g = lane >> 2, tg = lane & 3;

    const uint32_t a0 = smem_u32(sA4);
    const uint32_t b0 = smem_u32(sB4);

    auto load_kc = [&](int kc) {
        int s = kc & 3;
        int k0 = kc * 32;
        uint32_t aDst = a0 + s * (GA_W * 4);
        uint32_t bDst = b0 + s * (GB_W * 4);
#pragma unroll
        for (int i = 0; i < 2; i++) {
            int idx = tid + i * 256;
            int row = idx >> 3, seg = idx & 7;
            cp16(aDst + (row * 36 + seg * 4) * 4, A + (size_t)row * lda + k0 + seg * 4);
        }
#pragma unroll
        for (int i = 0; i < 4; i++) {
            int idx = tid + i * 256;
            int rb = idx >> 5, c4 = idx & 31;
            cp16(bDst + (rb * 132 + c4 * 4) * 4, B + (size_t)(k0 + rb) * N + col0 + c4 * 4);
        }
    };

    float c[2][4][4];
#pragma unroll
    for (int a = 0; a < 2; a++)
#pragma unroll
        for (int b2 = 0; b2 < 4; b2++)
#pragma unroll
            for (int d = 0; d < 4; d++) c[a][b2][d] = 0.f;

    const int NK = Kloop / 32;
    load_kc(0); CP_COMMIT();
    if (NK > 1) load_kc(1);
    CP_COMMIT();
    if (NK > 2) load_kc(2);
    CP_COMMIT();

    for (int kc = 0; kc < NK; kc++) {
        int s = kc & 3;
        CP_WAIT2();                 // 3 groups in flight; drain oldest (kc)
        __syncthreads();
        if (kc + 3 < NK) load_kc(kc + 3);
        CP_COMMIT();                // keep 3 groups pending

        const float* pA = sA4 + s * GA_W;
        const float* pB = sB4 + s * GB_W;
#pragma unroll
        for (int ks = 0; ks < 4; ks++) {
            const int kb = ks * 8;
            unsigned af[2][4], bf[4][2];
#pragma unroll
            for (int mt = 0; mt < 2; mt++) {
                int r = wm * 32 + mt * 16 + g;
                af[mt][0] = f2tf32(pA[r * 36 + kb + tg]);
                af[mt][1] = f2tf32(pA[(r + 8) * 36 + kb + tg]);
                af[mt][2] = f2tf32(pA[r * 36 + kb + tg + 4]);
                af[mt][3] = f2tf32(pA[(r + 8) * 36 + kb + tg + 4]);
            }
#pragma unroll
            for (int nt = 0; nt < 4; nt++) {
                int col = wn * 32 + nt * 8 + g;
                bf[nt][0] = f2tf32(pB[(kb + tg) * 132 + col]);
                bf[nt][1] = f2tf32(pB[(kb + tg + 4) * 132 + col]);
            }
#pragma unroll
            for (int mt = 0; mt < 2; mt++)
#pragma unroll
                for (int nt = 0; nt < 4; nt++) MMA_TF32(c[mt][nt], af[mt], bf[nt]);
        }
    }
#pragma unroll
    for (int mt = 0; mt < 2; mt++)
#pragma unroll
        for (int nt = 0; nt < 4; nt++) {
            int r = wm * 32 + mt * 16 + g;
            int col = col0 + wn * 32 + nt * 8 + tg * 2;
            float add0 = 0.f, add1 = 0.f;
            if (EPI == 1) { add0 = bias[col]; add1 = bias[col + 1]; }
            C[(size_t)r * N + col] = c[mt][nt][0] + add0;
            C[(size_t)r * N + col + 1] = c[mt][nt][1] + add1;
            C[(size_t)(r + 8) * N + col] = c[mt][nt][2] + add0;
            C[(size_t)(r + 8) * N + col + 1] = c[mt][nt][3] + add1;
        }
}

template <int EPI>
__global__ __launch_bounds__(256, 2) void k_gemm(const float* __restrict__ A,
                                                 const float* __restrict__ B,
                                                 const float* __restrict__ bias,
                                                 float* __restrict__ C, int K, int N) {
    gemm_body<EPI>(A, B, bias, C, K, K, N, blockIdx.x * 128);
}

// split-K paired GEMM: grid (N/128, 2 pairs, NSPLIT splits)
__global__ __launch_bounds__(256, 2) void k_gemm_splitk(
    const float* A0, const float* A1, const float* B0, const float* B1,
    float* Cp, int K, int N) {
    const int pair = blockIdx.y, z = blockIdx.z;
    const float* A = pair ? A1 : A0;
    const float* B = pair ? B1 : B0;
    const int Ks = K / NSPLIT;
    float* C = Cp + ((size_t)z * 2 + pair) * XSEG;
    gemm_body<0>(A + z * Ks, B + (size_t)z * Ks * N, nullptr, C,
                 K, Ks, N, blockIdx.x * 128);
}

// ---------------- k_gru_pair : sums NSPLIT split-K partials + pointwise GRU --
// float4 over u: 256 threads x 4 = 1024 = UU
__global__ void k_gru_pair(const float* xgp, const float* b0v, const float* b1v,
                           float* o0, float* o1, float* y0, float* y1) {
    const int pair = blockIdx.y;
    const float* xg = xgp + (size_t)pair * XSEG;
    const float* bvec = pair ? b1v : b0v;
    float* hout = pair ? o1 : o0;
    float* yout = pair ? y1 : y0;
    int b = blockIdx.x;
    const size_t ZS = 2 * (size_t)XSEG;
    int u = threadIdx.x * 4;
    size_t iz = (size_t)b * 3 * UU + u;
    size_t ir = iz + UU, ih = iz + 2 * UU;

    float4 xz = make_float4(0.f, 0.f, 0.f, 0.f);
    float4 xr = xz, xh = xz;
#pragma unroll
    for (int z = 0; z < NSPLIT; z++) {
        float4 pz = *reinterpret_cast<const float4*>(xg + iz + z * ZS);
        float4 pr = *reinterpret_cast<const float4*>(xg + ir + z * ZS);
        float4 ph = *reinterpret_cast<const float4*>(xg + ih + z * ZS);
        xz.x += pz.x; xz.y += pz.y; xz.z += pz.z; xz.w += pz.w;
        xr.x += pr.x; xr.y += pr.y; xr.z += pr.z; xr.w += pr.w;
        xh.x += ph.x; xh.y += ph.y; xh.z += ph.z; xh.w += ph.w;
    }
    float4 b0z = *reinterpret_cast<const float4*>(bvec + u);
    float4 b0r = *reinterpret_cast<const float4*>(bvec + UU + u);
    float4 b0h = *reinterpret_cast<const float4*>(bvec + 2 * UU + u);
    float4 b1z = *reinterpret_cast<const float4*>(bvec + 3 * UU + u);
    float4 b1r = *reinterpret_cast<const float4*>(bvec + 3 * UU + UU + u);
    float4 b1h = *reinterpret_cast<const float4*>(bvec + 3 * UU + 2 * UU + u);

    float4 hres;
    {
        float vz[4] = {xz.x + b0z.x + b1z.x, xz.y + b0z.y + b1z.y,
                       xz.z + b0z.z + b1z.z, xz.w + b0z.w + b1z.w};
        float vr[4] = {xr.x + b0r.x + b1r.x, xr.y + b0r.y + b1r.y,
                       xr.z + b0r.z + b1r.z, xr.w + b0r.w + b1r.w};
        float vh[4] = {xh.x + b0h.x, xh.y + b0h.y, xh.z + b0h.z, xh.w + b0h.w};
        float v1h[4] = {b1h.x, b1h.y, b1h.z, b1h.w};
        float* hr = reinterpret_cast<float*>(&hres);
#pragma unroll
        for (int q = 0; q < 4; q++) {
            float z = 1.f / (1.f + expf(-vz[q]));
            float r = 1.f / (1.f + expf(-vr[q]));
            float hc = tanhf(vh[q] + r * v1h[q]);
            hr[q] = (1.f - z) * hc;
        }
    }
    *reinterpret_cast<float4*>(hout + b * UU + u) = hres;
    if (yout) *reinterpret_cast<float4*>(yout + b * 2 * UU + u) = hres;
}

// ---------------- host launcher ----------------------------------------------
extern "C" void kernel_launch(void* const* d_in, const int* in_sizes, int n_in,
                              void* d_out, int out_size) {
    (void)in_sizes; (void)n_in; (void)out_size;
    const int* x = (const int*)d_in[0];
    const float* state = (const float*)d_in[1];
    const float* enc = (const float*)d_in[2];
    const float* Wh = (const float*)d_in[3];
    const float* bh = (const float*)d_in[4];
    const float* Wc = (const float*)d_in[5];
    const float* bc = (const float*)d_in[6];
    const float* Ws = (const float*)d_in[7];
    const float* bs = (const float*)d_in[8];
    const float* emb = (const float*)d_in[9];
    const float* fw0_k = (const float*)d_in[10];
    const float* fw0_b = (const float*)d_in[12];
    const float* fw1_k = (const float*)d_in[13];
    const float* fw1_b = (const float*)d_in[15];
    const float* bw0_k = (const float*)d_in[16];
    const float* bw0_b = (const float*)d_in[18];
    const float* bw1_k = (const float*)d_in[19];
    const float* bw1_b = (const float*)d_in[21];
    const float* fcW = (const float*)d_in[22];
    const float* fcb = (const float*)d_in[23];

    float* out = (float*)d_out;
    float* h0f = out + (size_t)BB * VV;
    float* h1f = h0f + BB * UU;
    float* h0b = h1f + BB * UU;
    float* h1b = h0b + BB * UU;

    float *p_xin, *p_xgp, *p_y;
    cudaGetSymbolAddress((void**)&p_xin, g_xin);
    cudaGetSymbolAddress((void**)&p_xgp, g_xgp);
    cudaGetSymbolAddress((void**)&p_y, g_y);

    cudaFuncSetAttribute(k_score, cudaFuncAttributeMaxDynamicSharedMemorySize, SC_SMEM);
    cudaFuncSetAttribute(k_gemm<1>, cudaFuncAttributeMaxDynamicSharedMemorySize, GB_SMEM);
    cudaFuncSetAttribute(k_gemm_splitk, cudaFuncAttributeMaxDynamicSharedMemorySize, GB_SMEM);

    // attention
    k_prep<<<PREP_TOTAL, 256>>>(Wc, state, Wh, bh);
    k_score<<<MROWS / 128, 256, SC_SMEM>>>(enc, bc, Ws);
    k_softmax<<<BB, 256>>>(bs);
    k_ctx<<<dim3(ENCD / 512, BB, NSEG), 256>>>();
    k_xin<<<BB, 256>>>(x, emb);

    // GRU stacks (zero hidden state => rk unused); fw/bw paired, split-K x8
    k_gemm_splitk<<<dim3(3 * UU / 128, 2, NSPLIT), 256, GB_SMEM>>>(
        p_xin, p_xin, fw0_k, bw0_k, p_xgp, IN0, 3 * UU);
    k_gru_pair<<<dim3(BB, 2), 256>>>(p_xgp, fw0_b, bw0_b, h0f, h0b, nullptr, nullptr);
    k_gemm_splitk<<<dim3(3 * UU / 128, 2, NSPLIT), 256, GB_SMEM>>>(
        h0f, h0b, fw1_k, bw1_k, p_xgp, UU, 3 * UU);
    k_gru_pair<<<dim3(BB, 2), 256>>>(p_xgp, fw1_b, bw1_b, h1f, h1b,
                                     p_y, p_y + UU);

    // output projection
    k_gemm<1><<<dim3(VV / 128, 1), 256, GB_SMEM>>>(p_y, fcW, fcb, out, 2 * UU, VV);
}

// round 16
// speedup vs baseline: 1.0414x; 1.0032x over previous
#include <cuda_runtime.h>
#include <cuda_fp16.h>
#include <cstdint>

// Problem constants
#define BB   64
#define SRC  2048
#define ENCD 1024
#define UU   1024
#define EE   512
#define VV   32000
#define IN0  (ENCD + EE)        // 1536
#define MROWS (BB * SRC)        // 131072
#define XSEG (BB * 3 * UU)      // one gate-preact buffer
#define NSPLIT 8
#define NSEG 16

// ---------------- scratch (device globals; no allocation allowed) -----------
__device__ float  g_h[BB * UU];
__device__ __half g_encH[(size_t)MROWS * ENCD];   // enc in fp16 (256MB)
__device__ __half g_WcTH[ENCD * UU];              // Wc transposed fp16
__device__ float  g_s[MROWS];                     // scores
__device__ float  g_w[BB * SRC];                  // softmax weights
__device__ float  g_ctxp[NSEG][BB][ENCD];
__device__ float  g_xin[BB * IN0];
__device__ float  g_xgp[NSPLIT][2][XSEG];         // split-K partials
__device__ float  g_y[BB * 2 * UU];

// ---------------- helpers ----------------------------------------------------
__device__ __forceinline__ unsigned f2tf32(float f) {
    unsigned u;
    asm("cvt.rna.tf32.f32 %0, %1;" : "=r"(u) : "f"(f));
    return u;
}
__device__ __forceinline__ float htanh(float x) {
    float r;
    asm("tanh.approx.f32 %0, %1;" : "=f"(r) : "f"(x));
    return r;
}
__device__ __forceinline__ uint32_t smem_u32(const void* p) {
    uint32_t a;
    asm("{ .reg .u64 t; cvta.to.shared.u64 t, %1; cvt.u32.u64 %0, t; }" : "=r"(a) : "l"(p));
    return a;
}
__device__ __forceinline__ void cp16(uint32_t dst, const void* src) {
    asm volatile("cp.async.cg.shared.global [%0], [%1], 16;\n" :: "r"(dst), "l"(src));
}
#define CP_COMMIT() asm volatile("cp.async.commit_group;" ::: "memory")
#define CP_WAIT0()  asm volatile("cp.async.wait_group 0;" ::: "memory")
#define CP_WAIT1()  asm volatile("cp.async.wait_group 1;" ::: "memory")
#define CP_WAIT2()  asm volatile("cp.async.wait_group 2;" ::: "memory")

#define LDSM4(r0, r1, r2, r3, addr)                                              \
    asm volatile("ldmatrix.sync.aligned.m8n8.x4.shared.b16 {%0,%1,%2,%3}, [%4];" \
                 : "=r"(r0), "=r"(r1), "=r"(r2), "=r"(r3) : "r"(addr))

// fp16 mma m16n8k16 with fp32 accumulate
#define MMA_F16(c, a, b)                                                         \
    asm volatile(                                                                \
        "mma.sync.aligned.m16n8k16.row.col.f32.f16.f16.f32 "                     \
        "{%0,%1,%2,%3},{%4,%5,%6,%7},{%8,%9},{%0,%1,%2,%3};\n"                   \
        : "+f"((c)[0]), "+f"((c)[1]), "+f"((c)[2]), "+f"((c)[3])                 \
        : "r"((a)[0]), "r"((a)[1]), "r"((a)[2]), "r"((a)[3]),                    \
          "r"((b)[0]), "r"((b)[1]))

// tf32 mma m16n8k8 (small GEMMs)
#define MMA_TF32(c, a, b)                                                        \
    asm volatile(                                                                \
        "mma.sync.aligned.m16n8k8.row.col.f32.tf32.tf32.f32 "                    \
        "{%0,%1,%2,%3},{%4,%5,%6,%7},{%8,%9},{%0,%1,%2,%3};\n"                   \
        : "+f"((c)[0]), "+f"((c)[1]), "+f"((c)[2]), "+f"((c)[3])                 \
        : "r"((a)[0]), "r"((a)[1]), "r"((a)[2]), "r"((a)[3]),                    \
          "r"((b)[0]), "r"((b)[1]))

// ---------------- k_prep : Wc transpose | h = state@Wh+bh (4-way col split) --
#define PREP_TR_BLKS 1024
#define PREP_TOTAL (PREP_TR_BLKS + BB * 4)

__global__ void k_prep(const float* __restrict__ Wc,
                       const float* __restrict__ state, const float* __restrict__ Wh,
                       const float* __restrict__ bh) {
    __shared__ float sbuf[32 * 33];
    const int bx = blockIdx.x, tid = threadIdx.x;

    if (bx < PREP_TR_BLKS) {
        int j0 = (bx & 31) * 32, k0 = (bx >> 5) * 32;
        int lx = tid & 31, ly = tid >> 5;
        float (*t)[33] = reinterpret_cast<float(*)[33]>(sbuf);
#pragma unroll
        for (int i = 0; i < 4; i++) {
            int kk = ly + i * 8;
            t[kk][lx] = Wc[(size_t)(k0 + kk) * UU + j0 + lx];
        }
        __syncthreads();
#pragma unroll
        for (int i = 0; i < 4; i++) {
            int jj = ly + i * 8;
            g_WcTH[(size_t)(j0 + jj) * ENCD + k0 + lx] = __float2half_rn(t[lx][jj]);
        }
    } else {
        int idx = bx - PREP_TR_BLKS;
        int b = idx >> 2, jq = idx & 3;
        float* ss = sbuf;
        for (int i = tid; i < UU; i += 256) ss[i] = state[b * UU + i];
        __syncthreads();
        int col = jq * 256 + tid;
        float a0 = 0.f, a1 = 0.f, a2 = 0.f, a3 = 0.f;
#pragma unroll 2
        for (int k = 0; k < UU; k += 4) {
            a0 += ss[k] * Wh[(size_t)k * UU + col];
            a1 += ss[k + 1] * Wh[(size_t)(k + 1) * UU + col];
            a2 += ss[k + 2] * Wh[(size_t)(k + 2) * UU + col];
            a3 += ss[k + 3] * Wh[(size_t)(k + 3) * UU + col];
        }
        g_h[b * UU + col] = (a0 + a1) + (a2 + a3) + bh[col];
    }
}

// ---------------- k_score : fp16 mma, BK=64, asymmetric 3A/2B staging -------
// (R9/R13 configuration: 256 threads, warp tile 64x32, occ 2, grid 1024)
#define SKW 36                   // smem row stride in words (32 data + 4 pad)
#define STGW (128 * SKW)
#define STGB (STGW * 4)          // 18432 bytes per stage
#define SC_SMEM ((3 + 2) * STGB + (1024 + 1024 + 128) * 4)

__global__ __launch_bounds__(256, 2) void k_score(const float* __restrict__ enc,
                                                  const float* __restrict__ bc,
                                                  const float* __restrict__ Ws) {
    extern __shared__ char dsm[];
    uint32_t* sAp = reinterpret_cast<uint32_t*>(dsm);          // 3 stages
    uint32_t* sBp = sAp + 3 * STGW;                            // 2 stages
    float* shb = reinterpret_cast<float*>(sBp + 2 * STGW);     // [1024]
    float* sws = shb + 1024;                                   // [1024]
    float* srow = sws + 1024;                                  // [128]

    const int tid = threadIdx.x, wid = tid >> 5, lane = tid & 31;
    const int wm = wid & 1, wn = wid >> 1;
    const int g = lane >> 2, tg = lane & 3;
    const int R0 = blockIdx.x * 128;
    const int bidx = blockIdx.x >> 4;

    if (tid < 128) srow[tid] = 0.f;

    // prologue: convert own block fp32 -> fp16; fill shb/sws tables
    {
        const float* aF = enc + (size_t)R0 * ENCD;
        __half* aHw = g_encH + (size_t)R0 * ENCD;
#pragma unroll 4
        for (int i = tid; i < 128 * ENCD / 8; i += 256) {
            size_t off = (size_t)i * 8;
            float4 v0 = *reinterpret_cast<const float4*>(aF + off);
            float4 v1 = *reinterpret_cast<const float4*>(aF + off + 4);
            __half2 h[4];
            h[0] = __floats2half2_rn(v0.x, v0.y);
            h[1] = __floats2half2_rn(v0.z, v0.w);
            h[2] = __floats2half2_rn(v1.x, v1.y);
            h[3] = __floats2half2_rn(v1.z, v1.w);
            *reinterpret_cast<uint4*>(aHw + off) = *reinterpret_cast<uint4*>(h);
        }
#pragma unroll
        for (int i = tid; i < 1024; i += 256) {
            shb[i] = g_h[bidx * UU + i] + bc[i];
            sws[i] = Ws[i];
        }
        __threadfence();
        __syncthreads();
    }

    const uint32_t sA0 = smem_u32(sAp);
    const uint32_t sB0 = smem_u32(sBp);
    const __half* aBase = g_encH + (size_t)R0 * ENCD;

    uint32_t aOff[4], bOff[2];
#pragma unroll
    for (int mt = 0; mt < 4; mt++) {
        int row = wm * 64 + mt * 16 + ((lane >> 3) & 1) * 8 + (lane & 7);
        aOff[mt] = (row * SKW + ((lane >> 4) << 2)) * 4;
    }
#pragma unroll
    for (int np = 0; np < 2; np++) {
        int row = wn * 32 + np * 16 + ((lane >> 4) & 1) * 8 + (lane & 7);
        bOff[np] = (row * SKW + (((lane >> 3) & 1) << 2)) * 4;
    }

    // loaders: A stage = it % 3, B stage = it & 1
    auto load_A = [&](int it, int sa) {
        int kc = it & 15;
        const __half* aSrc = aBase + kc * 64;
        uint32_t aDst = sA0 + sa * STGB;
#pragma unroll
        for (int i = 0; i < 4; i++) {
            int idx = tid + i * 256;
            int row = idx >> 3, seg = idx & 7;
            cp16(aDst + (row * SKW + seg * 4) * 4, aSrc + (size_t)row * ENCD + seg * 8);
        }
    };
    auto load_B = [&](int it) {
        int kc = it & 15, jt = it >> 4;
        const __half* bSrc = g_WcTH + (size_t)(jt * 128) * ENCD + kc * 64;
        uint32_t bDst = sB0 + (it & 1) * STGB;
#pragma unroll
        for (int i = 0; i < 4; i++) {
            int idx = tid + i * 256;
            int row = idx >> 3, seg = idx & 7;
            cp16(bDst + (row * SKW + seg * 4) * 4, bSrc + (size_t)row * ENCD + seg * 8);
        }
    };

    float c[4][4][4];
#pragma unroll
    for (int a = 0; a < 4; a++)
#pragma unroll
        for (int b2 = 0; b2 < 4; b2++)
#pragma unroll
            for (int d = 0; d < 4; d++) c[a][b2][d] = 0.f;
    float rowacc[4][2] = {{0.f, 0.f}, {0.f, 0.f}, {0.f, 0.f}, {0.f, 0.f}};

    // prologue groups (FIFO): [B0][A0][A1]
    load_B(0); CP_COMMIT();
    load_A(0, 0); CP_COMMIT();
    load_A(1, 1); CP_COMMIT();

    const int TOT = 128;
    int sa = 0;                   // it % 3
    int sa2 = 2;                  // (it+2) % 3
    for (int it = 0; it < TOT; it++) {
        const int kc = it & 15;
        // pending (oldest->newest): A(it), B(it), A(it+1) -> drain first two
        if (it == TOT - 1) { CP_WAIT0(); } else { CP_WAIT1(); }
        __syncthreads();

        if (it + 1 < TOT) { load_B(it + 1); CP_COMMIT(); }
        if (it + 2 < TOT) { load_A(it + 2, sa2); CP_COMMIT(); }

        const uint32_t aB = sA0 + sa * STGB;
        const uint32_t bB = sB0 + (it & 1) * STGB;
#pragma unroll
        for (int ks = 0; ks < 4; ks++) {
            uint32_t bf[4][2];
#pragma unroll
            for (int np = 0; np < 2; np++)
                LDSM4(bf[2 * np][0], bf[2 * np][1], bf[2 * np + 1][0], bf[2 * np + 1][1],
                      bB + bOff[np] + ks * 32);
#pragma unroll
            for (int mt = 0; mt < 4; mt++) {
                uint32_t af[4];
                LDSM4(af[0], af[1], af[2], af[3], aB + aOff[mt] + ks * 32);
#pragma unroll
                for (int nt = 0; nt < 4; nt++) MMA_F16(c[mt][nt], af, bf[nt]);
            }
        }

        if (kc == 15) {
            const int jt = it >> 4;
            const float* hb8 = shb + jt * 128;
            const float* ws8 = sws + jt * 128;
#pragma unroll
            for (int mt = 0; mt < 4; mt++) {
                float rs0 = 0.f, rs1 = 0.f;
#pragma unroll
                for (int nt = 0; nt < 4; nt++) {
                    int nl = wn * 32 + nt * 8 + tg * 2;
#pragma unroll
                    for (int cc = 0; cc < 2; cc++) {
                        float hb = hb8[nl + cc], ws = ws8[nl + cc];
                        rs0 += htanh(c[mt][nt][cc] + hb) * ws;
                        rs1 += htanh(c[mt][nt][2 + cc] + hb) * ws;
                    }
                }
                rs0 += __shfl_xor_sync(0xffffffffu, rs0, 1);
                rs0 += __shfl_xor_sync(0xffffffffu, rs0, 2);
                rs1 += __shfl_xor_sync(0xffffffffu, rs1, 1);
                rs1 += __shfl_xor_sync(0xffffffffu, rs1, 2);
                rowacc[mt][0] += rs0;
                rowacc[mt][1] += rs1;
#pragma unroll
                for (int nt = 0; nt < 4; nt++)
#pragma unroll
                    for (int d = 0; d < 4; d++) c[mt][nt][d] = 0.f;
            }
        }

        sa = (sa == 2) ? 0 : sa + 1;
        sa2 = (sa2 == 2) ? 0 : sa2 + 1;
    }

#pragma unroll
    for (int mt = 0; mt < 4; mt++) {
        if (tg == 0) {
            atomicAdd(&srow[wm * 64 + mt * 16 + g], rowacc[mt][0]);
            atomicAdd(&srow[wm * 64 + mt * 16 + 8 + g], rowacc[mt][1]);
        }
    }
    __syncthreads();
    if (tid < 128) g_s[R0 + tid] = srow[tid];
}

// ---------------- k_softmax ---------------------------------------------------
__global__ void k_softmax(const float* __restrict__ bs) {
    __shared__ float sv[SRC];
    __shared__ float red[256];
    int b = blockIdx.x, tid = threadIdx.x;
    float bsv = bs[0];
    float lmax = -1e30f;
    for (int t = tid; t < SRC; t += 256) {
        float s = bsv + g_s[b * SRC + t];
        sv[t] = s;
        lmax = fmaxf(lmax, s);
    }
    red[tid] = lmax;
    __syncthreads();
    for (int off = 128; off; off >>= 1) {
        if (tid < off) red[tid] = fmaxf(red[tid], red[tid + off]);
        __syncthreads();
    }
    float m = red[0];
    __syncthreads();
    float lsum = 0.f;
    for (int t = tid; t < SRC; t += 256) {
        float e = __expf(sv[t] - m);
        sv[t] = e;
        lsum += e;
    }
    red[tid] = lsum;
    __syncthreads();
    for (int off = 128; off; off >>= 1) {
        if (tid < off) red[tid] += red[tid + off];
        __syncthreads();
    }
    float inv = 1.f / red[0];
    for (int t = tid; t < SRC; t += 256) g_w[b * SRC + t] = sv[t] * inv;
}

// ---------------- k_ctx : 16-way segmented weighted sum, half2 loads ---------
// grid: (ENCD/512, BB, 16); t-block = 128
__global__ void k_ctx() {
    __shared__ float sw[128];
    int b = blockIdx.y, seg = blockIdx.z;
    int k2 = blockIdx.x * 256 + threadIdx.x;     // half2 column index
    int t0 = seg * 128;
    if (threadIdx.x < 128) sw[threadIdx.x] = g_w[b * SRC + t0 + threadIdx.x];
    __syncthreads();
    const __half2* ep = reinterpret_cast<const __half2*>(
                            g_encH + ((size_t)b * SRC + t0) * ENCD) + k2;
    float ax0 = 0.f, ay0 = 0.f, ax1 = 0.f, ay1 = 0.f;
    float ax2 = 0.f, ay2 = 0.f, ax3 = 0.f, ay3 = 0.f;
    for (int t = 0; t < 128; t += 8) {
#pragma unroll
        for (int u = 0; u < 8; u += 4) {
            float2 v0 = __half22float2(ep[(size_t)(t + u) * (ENCD / 2)]);
            float2 v1 = __half22float2(ep[(size_t)(t + u + 1) * (ENCD / 2)]);
            float2 v2 = __half22float2(ep[(size_t)(t + u + 2) * (ENCD / 2)]);
            float2 v3 = __half22float2(ep[(size_t)(t + u + 3) * (ENCD / 2)]);
            float w0 = sw[t + u], w1 = sw[t + u + 1];
            float w2 = sw[t + u + 2], w3 = sw[t + u + 3];
            ax0 += w0 * v0.x; ay0 += w0 * v0.y;
            ax1 += w1 * v1.x; ay1 += w1 * v1.y;
            ax2 += w2 * v2.x; ay2 += w2 * v2.y;
            ax3 += w3 * v3.x; ay3 += w3 * v3.y;
        }
    }
    g_ctxp[seg][b][2 * k2] = (ax0 + ax1) + (ax2 + ax3);
    g_ctxp[seg][b][2 * k2 + 1] = (ay0 + ay1) + (ay2 + ay3);
}

// ---------------- k_xin : xin = concat(sum(ctx partials), emb[x]), float4 ----
__global__ void k_xin(const int* __restrict__ x, const float* __restrict__ emb) {
    int b = blockIdx.x;
    int xi = x[b];
    for (int i4 = threadIdx.x; i4 < IN0 / 4; i4 += 256) {
        float4 v;
        if (i4 < ENCD / 4) {
            v = make_float4(0.f, 0.f, 0.f, 0.f);
#pragma unroll
            for (int seg = 0; seg < NSEG; seg++) {
                float4 p = *reinterpret_cast<const float4*>(&g_ctxp[seg][b][i4 * 4]);
                v.x += p.x; v.y += p.y; v.z += p.z; v.w += p.w;
            }
        } else {
            v = *reinterpret_cast<const float4*>(
                    emb + (size_t)xi * EE + (i4 * 4 - ENCD));
        }
        *reinterpret_cast<float4*>(&g_xin[b * IN0 + i4 * 4]) = v;
    }
}

// ---------------- tf32 GEMM body, 4-stage cp.async, cvt-in-fragment ---------
#define GA_W (64 * 36)
#define GB_W (32 * 132)
#define GB_SMEM (4 * (GA_W + GB_W) * 4)

template <int EPI>
__device__ __forceinline__ void gemm_body(const float* __restrict__ A,
                                          const float* __restrict__ B,
                                          const float* __restrict__ bias,
                                          float* __restrict__ C,
                                          int lda, int Kloop, int N, int col0) {
    extern __shared__ float gsm[];
    float* sA4 = gsm;                 // 4 x GA_W
    float* sB4 = gsm + 4 * GA_W;      // 4 x GB_W
    const int tid = threadIdx.x;
    const int wid = tid >> 5, lane = tid & 31;
    const int wm = wid & 1, wn = wid >> 1;
    const int g = lane >> 2, tg = lane & 3;

    const uint32_t a0 = smem_u32(sA4);
    const uint32_t b0 = smem_u32(sB4);

    auto load_kc = [&](int kc) {
        int s = kc & 3;
        int k0 = kc * 32;
        uint32_t aDst = a0 + s * (GA_W * 4);
        uint32_t bDst = b0 + s * (GB_W * 4);
#pragma unroll
        for (int i = 0; i < 2; i++) {
            int idx = tid + i * 256;
            int row = idx >> 3, seg = idx & 7;
            cp16(aDst + (row * 36 + seg * 4) * 4, A + (size_t)row * lda + k0 + seg * 4);
        }
#pragma unroll
        for (int i = 0; i < 4; i++) {
            int idx = tid + i * 256;
            int rb = idx >> 5, c4 = idx & 31;
            cp16(bDst + (rb * 132 + c4 * 4) * 4, B + (size_t)(k0 + rb) * N + col0 + c4 * 4);
        }
    };

    float c[2][4][4];
#pragma unroll
    for (int a = 0; a < 2; a++)
#pragma unroll
        for (int b2 = 0; b2 < 4; b2++)
#pragma unroll
            for (int d = 0; d < 4; d++) c[a][b2][d] = 0.f;

    const int NK = Kloop / 32;
    load_kc(0); CP_COMMIT();
    if (NK > 1) load_kc(1);
    CP_COMMIT();
    if (NK > 2) load_kc(2);
    CP_COMMIT();

    for (int kc = 0; kc < NK; kc++) {
        int s = kc & 3;
        CP_WAIT2();                 // 3 groups in flight; drain oldest (kc)
        __syncthreads();
        if (kc + 3 < NK) load_kc(kc + 3);
        CP_COMMIT();                // keep 3 groups pending

        const float* pA = sA4 + s * GA_W;
        const float* pB = sB4 + s * GB_W;
#pragma unroll
        for (int ks = 0; ks < 4; ks++) {
            const int kb = ks * 8;
            unsigned af[2][4], bf[4][2];
#pragma unroll
            for (int mt = 0; mt < 2; mt++) {
                int r = wm * 32 + mt * 16 + g;
                af[mt][0] = f2tf32(pA[r * 36 + kb + tg]);
                af[mt][1] = f2tf32(pA[(r + 8) * 36 + kb + tg]);
                af[mt][2] = f2tf32(pA[r * 36 + kb + tg + 4]);
                af[mt][3] = f2tf32(pA[(r + 8) * 36 + kb + tg + 4]);
            }
#pragma unroll
            for (int nt = 0; nt < 4; nt++) {
                int col = wn * 32 + nt * 8 + g;
                bf[nt][0] = f2tf32(pB[(kb + tg) * 132 + col]);
                bf[nt][1] = f2tf32(pB[(kb + tg + 4) * 132 + col]);
            }
#pragma unroll
            for (int mt = 0; mt < 2; mt++)
#pragma unroll
                for (int nt = 0; nt < 4; nt++) MMA_TF32(c[mt][nt], af[mt], bf[nt]);
        }
    }
#pragma unroll
    for (int mt = 0; mt < 2; mt++)
#pragma unroll
        for (int nt = 0; nt < 4; nt++) {
            int r = wm * 32 + mt * 16 + g;
            int col = col0 + wn * 32 + nt * 8 + tg * 2;
            float add0 = 0.f, add1 = 0.f;
            if (EPI == 1) { add0 = bias[col]; add1 = bias[col + 1]; }
            C[(size_t)r * N + col] = c[mt][nt][0] + add0;
            C[(size_t)r * N + col + 1] = c[mt][nt][1] + add1;
            C[(size_t)(r + 8) * N + col] = c[mt][nt][2] + add0;
            C[(size_t)(r + 8) * N + col + 1] = c[mt][nt][3] + add1;
        }
}

template <int EPI>
__global__ __launch_bounds__(256, 2) void k_gemm(const float* __restrict__ A,
                                                 const float* __restrict__ B,
                                                 const float* __restrict__ bias,
                                                 float* __restrict__ C, int K, int N) {
    gemm_body<EPI>(A, B, bias, C, K, K, N, blockIdx.x * 128);
}

// split-K paired GEMM: grid (N/128, 2 pairs, NSPLIT splits)
__global__ __launch_bounds__(256, 2) void k_gemm_splitk(
    const float* A0, const float* A1, const float* B0, const float* B1,
    float* Cp, int K, int N) {
    const int pair = blockIdx.y, z = blockIdx.z;
    const float* A = pair ? A1 : A0;
    const float* B = pair ? B1 : B0;
    const int Ks = K / NSPLIT;
    float* C = Cp + ((size_t)z * 2 + pair) * XSEG;
    gemm_body<0>(A + z * Ks, B + (size_t)z * Ks * N, nullptr, C,
                 K, Ks, N, blockIdx.x * 128);
}

// ---------------- k_gru_pair : sums NSPLIT split-K partials + pointwise GRU --
// float4 over u: 256 threads x 4 = 1024 = UU
__global__ void k_gru_pair(const float* xgp, const float* b0v, const float* b1v,
                           float* o0, float* o1, float* y0, float* y1) {
    const int pair = blockIdx.y;
    const float* xg = xgp + (size_t)pair * XSEG;
    const float* bvec = pair ? b1v : b0v;
    float* hout = pair ? o1 : o0;
    float* yout = pair ? y1 : y0;
    int b = blockIdx.x;
    const size_t ZS = 2 * (size_t)XSEG;
    int u = threadIdx.x * 4;
    size_t iz = (size_t)b * 3 * UU + u;
    size_t ir = iz + UU, ih = iz + 2 * UU;

    float4 xz = make_float4(0.f, 0.f, 0.f, 0.f);
    float4 xr = xz, xh = xz;
#pragma unroll
    for (int z = 0; z < NSPLIT; z++) {
        float4 pz = *reinterpret_cast<const float4*>(xg + iz + z * ZS);
        float4 pr = *reinterpret_cast<const float4*>(xg + ir + z * ZS);
        float4 ph = *reinterpret_cast<const float4*>(xg + ih + z * ZS);
        xz.x += pz.x; xz.y += pz.y; xz.z += pz.z; xz.w += pz.w;
        xr.x += pr.x; xr.y += pr.y; xr.z += pr.z; xr.w += pr.w;
        xh.x += ph.x; xh.y += ph.y; xh.z += ph.z; xh.w += ph.w;
    }
    float4 b0z = *reinterpret_cast<const float4*>(bvec + u);
    float4 b0r = *reinterpret_cast<const float4*>(bvec + UU + u);
    float4 b0h = *reinterpret_cast<const float4*>(bvec + 2 * UU + u);
    float4 b1z = *reinterpret_cast<const float4*>(bvec + 3 * UU + u);
    float4 b1r = *reinterpret_cast<const float4*>(bvec + 3 * UU + UU + u);
    float4 b1h = *reinterpret_cast<const float4*>(bvec + 3 * UU + 2 * UU + u);

    float4 hres;
    {
        float vz[4] = {xz.x + b0z.x + b1z.x, xz.y + b0z.y + b1z.y,
                       xz.z + b0z.z + b1z.z, xz.w + b0z.w + b1z.w};
        float vr[4] = {xr.x + b0r.x + b1r.x, xr.y + b0r.y + b1r.y,
                       xr.z + b0r.z + b1r.z, xr.w + b0r.w + b1r.w};
        float vh[4] = {xh.x + b0h.x, xh.y + b0h.y, xh.z + b0h.z, xh.w + b0h.w};
        float v1h[4] = {b1h.x, b1h.y, b1h.z, b1h.w};
        float* hr = reinterpret_cast<float*>(&hres);
#pragma unroll
        for (int q = 0; q < 4; q++) {
            float z = 1.f / (1.f + __expf(-vz[q]));
            float r = 1.f / (1.f + __expf(-vr[q]));
            float hc = tanhf(vh[q] + r * v1h[q]);
            hr[q] = (1.f - z) * hc;
        }
    }
    *reinterpret_cast<float4*>(hout + b * UU + u) = hres;
    if (yout) *reinterpret_cast<float4*>(yout + b * 2 * UU + u) = hres;
}

// ---------------- host launcher ----------------------------------------------
extern "C" void kernel_launch(void* const* d_in, const int* in_sizes, int n_in,
                              void* d_out, int out_size) {
    (void)in_sizes; (void)n_in; (void)out_size;
    const int* x = (const int*)d_in[0];
    const float* state = (const float*)d_in[1];
    const float* enc = (const float*)d_in[2];
    const float* Wh = (const float*)d_in[3];
    const float* bh = (const float*)d_in[4];
    const float* Wc = (const float*)d_in[5];
    const float* bc = (const float*)d_in[6];
    const float* Ws = (const float*)d_in[7];
    const float* bs = (const float*)d_in[8];
    const float* emb = (const float*)d_in[9];
    const float* fw0_k = (const float*)d_in[10];
    const float* fw0_b = (const float*)d_in[12];
    const float* fw1_k = (const float*)d_in[13];
    const float* fw1_b = (const float*)d_in[15];
    const float* bw0_k = (const float*)d_in[16];
    const float* bw0_b = (const float*)d_in[18];
    const float* bw1_k = (const float*)d_in[19];
    const float* bw1_b = (const float*)d_in[21];
    const float* fcW = (const float*)d_in[22];
    const float* fcb = (const float*)d_in[23];

    float* out = (float*)d_out;
    float* h0f = out + (size_t)BB * VV;
    float* h1f = h0f + BB * UU;
    float* h0b = h1f + BB * UU;
    float* h1b = h0b + BB * UU;

    float *p_xin, *p_xgp, *p_y;
    cudaGetSymbolAddress((void**)&p_xin, g_xin);
    cudaGetSymbolAddress((void**)&p_xgp, g_xgp);
    cudaGetSymbolAddress((void**)&p_y, g_y);

    cudaFuncSetAttribute(k_score, cudaFuncAttributeMaxDynamicSharedMemorySize, SC_SMEM);
    cudaFuncSetAttribute(k_gemm<1>, cudaFuncAttributeMaxDynamicSharedMemorySize, GB_SMEM);
    cudaFuncSetAttribute(k_gemm_splitk, cudaFuncAttributeMaxDynamicSharedMemorySize, GB_SMEM);

    // attention
    k_prep<<<PREP_TOTAL, 256>>>(Wc, state, Wh, bh);
    k_score<<<MROWS / 128, 256, SC_SMEM>>>(enc, bc, Ws);
    k_softmax<<<BB, 256>>>(bs);
    k_ctx<<<dim3(ENCD / 512, BB, NSEG), 256>>>();
    k_xin<<<BB, 256>>>(x, emb);

    // GRU stacks (zero hidden state => rk unused); fw/bw paired, split-K x8
    k_gemm_splitk<<<dim3(3 * UU / 128, 2, NSPLIT), 256, GB_SMEM>>>(
        p_xin, p_xin, fw0_k, bw0_k, p_xgp, IN0, 3 * UU);
    k_gru_pair<<<dim3(BB, 2), 256>>>(p_xgp, fw0_b, bw0_b, h0f, h0b, nullptr, nullptr);
    k_gemm_splitk<<<dim3(3 * UU / 128, 2, NSPLIT), 256, GB_SMEM>>>(
        h0f, h0b, fw1_k, bw1_k, p_xgp, UU, 3 * UU);
    k_gru_pair<<<dim3(BB, 2), 256>>>(p_xgp, fw1_b, bw1_b, h1f, h1b,
                                     p_y, p_y + UU);

    // output projection
    k_gemm<1><<<dim3(VV / 128, 1), 256, GB_SMEM>>>(p_y, fcW, fcb, out, 2 * UU, VV);
}

// round 17
// speedup vs baseline: 1.0975x; 1.0539x over previous
#include <cuda_runtime.h>
#include <cuda_fp16.h>
#include <cstdint>

// Problem constants
#define BB   64
#define SRC  2048
#define ENCD 1024
#define UU   1024
#define EE   512
#define VV   32000
#define IN0  (ENCD + EE)        // 1536
#define MROWS (BB * SRC)        // 131072
#define XSEG (BB * 3 * UU)      // one gate-preact buffer
#define NSPLIT 8
#define NSEG 16
#define HSPLIT 4

// ---------------- scratch (device globals; no allocation allowed) -----------
__device__ __half g_encH[(size_t)MROWS * ENCD];   // enc in fp16 (256MB)
__device__ __half g_WcTH[ENCD * UU];              // Wc transposed fp16
__device__ float  g_s[MROWS];                     // scores
__device__ float  g_w[BB * SRC];                  // softmax weights
__device__ float  g_ctxp[NSEG][BB][ENCD];
__device__ float  g_xin[BB * IN0];
__device__ float  g_xgp[NSPLIT][2][XSEG];         // split-K partials (also h partials)
__device__ float  g_y[BB * 2 * UU];

// ---------------- helpers ----------------------------------------------------
__device__ __forceinline__ unsigned f2tf32(float f) {
    unsigned u;
    asm("cvt.rna.tf32.f32 %0, %1;" : "=r"(u) : "f"(f));
    return u;
}
__device__ __forceinline__ float htanh(float x) {
    float r;
    asm("tanh.approx.f32 %0, %1;" : "=f"(r) : "f"(x));
    return r;
}
__device__ __forceinline__ uint32_t smem_u32(const void* p) {
    uint32_t a;
    asm("{ .reg .u64 t; cvta.to.shared.u64 t, %1; cvt.u32.u64 %0, t; }" : "=r"(a) : "l"(p));
    return a;
}
__device__ __forceinline__ void cp16(uint32_t dst, const void* src) {
    asm volatile("cp.async.cg.shared.global [%0], [%1], 16;\n" :: "r"(dst), "l"(src));
}
#define CP_COMMIT() asm volatile("cp.async.commit_group;" ::: "memory")
#define CP_WAIT0()  asm volatile("cp.async.wait_group 0;" ::: "memory")
#define CP_WAIT1()  asm volatile("cp.async.wait_group 1;" ::: "memory")
#define CP_WAIT2()  asm volatile("cp.async.wait_group 2;" ::: "memory")

#define LDSM4(r0, r1, r2, r3, addr)                                              \
    asm volatile("ldmatrix.sync.aligned.m8n8.x4.shared.b16 {%0,%1,%2,%3}, [%4];" \
                 : "=r"(r0), "=r"(r1), "=r"(r2), "=r"(r3) : "r"(addr))

#define MMA_F16(c, a, b)                                                         \
    asm volatile(                                                                \
        "mma.sync.aligned.m16n8k16.row.col.f32.f16.f16.f32 "                     \
        "{%0,%1,%2,%3},{%4,%5,%6,%7},{%8,%9},{%0,%1,%2,%3};\n"                   \
        : "+f"((c)[0]), "+f"((c)[1]), "+f"((c)[2]), "+f"((c)[3])                 \
        : "r"((a)[0]), "r"((a)[1]), "r"((a)[2]), "r"((a)[3]),                    \
          "r"((b)[0]), "r"((b)[1]))

#define MMA_TF32(c, a, b)                                                        \
    asm volatile(                                                                \
        "mma.sync.aligned.m16n8k8.row.col.f32.tf32.tf32.f32 "                    \
        "{%0,%1,%2,%3},{%4,%5,%6,%7},{%8,%9},{%0,%1,%2,%3};\n"                   \
        : "+f"((c)[0]), "+f"((c)[1]), "+f"((c)[2]), "+f"((c)[3])                 \
        : "r"((a)[0]), "r"((a)[1]), "r"((a)[2]), "r"((a)[3]),                    \
          "r"((b)[0]), "r"((b)[1]))

// ---------------- k_prep : Wc transpose only (grid 1024) ---------------------
__global__ void k_prep(const float* __restrict__ Wc) {
    __shared__ float t[32][33];
    const int bx = blockIdx.x, tid = threadIdx.x;
    int j0 = (bx & 31) * 32, k0 = (bx >> 5) * 32;
    int lx = tid & 31, ly = tid >> 5;
#pragma unroll
    for (int i = 0; i < 4; i++) {
        int kk = ly + i * 8;
        t[kk][lx] = Wc[(size_t)(k0 + kk) * UU + j0 + lx];
    }
    __syncthreads();
#pragma unroll
    for (int i = 0; i < 4; i++) {
        int jj = ly + i * 8;
        g_WcTH[(size_t)(j0 + jj) * ENCD + k0 + lx] = __float2half_rn(t[lx][jj]);
    }
}

// ---------------- k_score : fp16 mma, BK=64, asymmetric 3A/2B staging -------
#define SKW 36
#define STGW (128 * SKW)
#define STGB (STGW * 4)
#define SC_SMEM ((3 + 2) * STGB + (1024 + 1024 + 128) * 4)

__global__ __launch_bounds__(256, 2) void k_score(const float* __restrict__ enc,
                                                  const float* __restrict__ hp,
                                                  const float* __restrict__ bh,
                                                  const float* __restrict__ bc,
                                                  const float* __restrict__ Ws) {
    extern __shared__ char dsm[];
    uint32_t* sAp = reinterpret_cast<uint32_t*>(dsm);
    uint32_t* sBp = sAp + 3 * STGW;
    float* shb = reinterpret_cast<float*>(sBp + 2 * STGW);
    float* sws = shb + 1024;
    float* srow = sws + 1024;

    const int tid = threadIdx.x, wid = tid >> 5, lane = tid & 31;
    const int wm = wid & 1, wn = wid >> 1;
    const int g = lane >> 2, tg = lane & 3;
    const int R0 = blockIdx.x * 128;
    const int bidx = blockIdx.x >> 4;

    if (tid < 128) srow[tid] = 0.f;

    {
        const float* aF = enc + (size_t)R0 * ENCD;
        __half* aHw = g_encH + (size_t)R0 * ENCD;
#pragma unroll 4
        for (int i = tid; i < 128 * ENCD / 8; i += 256) {
            size_t off = (size_t)i * 8;
            float4 v0 = *reinterpret_cast<const float4*>(aF + off);
            float4 v1 = *reinterpret_cast<const float4*>(aF + off + 4);
            __half2 h[4];
            h[0] = __floats2half2_rn(v0.x, v0.y);
            h[1] = __floats2half2_rn(v0.z, v0.w);
            h[2] = __floats2half2_rn(v1.x, v1.y);
            h[3] = __floats2half2_rn(v1.z, v1.w);
            *reinterpret_cast<uint4*>(aHw + off) = *reinterpret_cast<uint4*>(h);
        }
#pragma unroll
        for (int i = tid; i < 1024; i += 256) {
            size_t hi = (size_t)bidx * UU + i;
            float hv = hp[hi] + hp[hi + (size_t)BB * UU]
                     + hp[hi + 2 * (size_t)BB * UU] + hp[hi + 3 * (size_t)BB * UU];
            shb[i] = hv + bh[i] + bc[i];
            sws[i] = Ws[i];
        }
        __threadfence();
        __syncthreads();
    }

    const uint32_t sA0 = smem_u32(sAp);
    const uint32_t sB0 = smem_u32(sBp);
    const __half* aBase = g_encH + (size_t)R0 * ENCD;

    uint32_t aOff[4], bOff[2];
#pragma unroll
    for (int mt = 0; mt < 4; mt++) {
        int row = wm * 64 + mt * 16 + ((lane >> 3) & 1) * 8 + (lane & 7);
        aOff[mt] = (row * SKW + ((lane >> 4) << 2)) * 4;
    }
#pragma unroll
    for (int np = 0; np < 2; np++) {
        int row = wn * 32 + np * 16 + ((lane >> 4) & 1) * 8 + (lane & 7);
        bOff[np] = (row * SKW + (((lane >> 3) & 1) << 2)) * 4;
    }

    auto load_A = [&](int it, int sa) {
        int kc = it & 15;
        const __half* aSrc = aBase + kc * 64;
        uint32_t aDst = sA0 + sa * STGB;
#pragma unroll
        for (int i = 0; i < 4; i++) {
            int idx = tid + i * 256;
            int row = idx >> 3, seg = idx & 7;
            cp16(aDst + (row * SKW + seg * 4) * 4, aSrc + (size_t)row * ENCD + seg * 8);
        }
    };
    auto load_B = [&](int it) {
        int kc = it & 15, jt = it >> 4;
        const __half* bSrc = g_WcTH + (size_t)(jt * 128) * ENCD + kc * 64;
        uint32_t bDst = sB0 + (it & 1) * STGB;
#pragma unroll
        for (int i = 0; i < 4; i++) {
            int idx = tid + i * 256;
            int row = idx >> 3, seg = idx & 7;
            cp16(bDst + (row * SKW + seg * 4) * 4, bSrc + (size_t)row * ENCD + seg * 8);
        }
    };

    float c[4][4][4];
#pragma unroll
    for (int a = 0; a < 4; a++)
#pragma unroll
        for (int b2 = 0; b2 < 4; b2++)
#pragma unroll
            for (int d = 0; d < 4; d++) c[a][b2][d] = 0.f;
    float rowacc[4][2] = {{0.f, 0.f}, {0.f, 0.f}, {0.f, 0.f}, {0.f, 0.f}};

    load_B(0); CP_COMMIT();
    load_A(0, 0); CP_COMMIT();
    load_A(1, 1); CP_COMMIT();

    const int TOT = 128;
    int sa = 0, sa2 = 2;
    for (int it = 0; it < TOT; it++) {
        const int kc = it & 15;
        if (it == TOT - 1) { CP_WAIT0(); } else { CP_WAIT1(); }
        __syncthreads();

        if (it + 1 < TOT) { load_B(it + 1); CP_COMMIT(); }
        if (it + 2 < TOT) { load_A(it + 2, sa2); CP_COMMIT(); }

        const uint32_t aB = sA0 + sa * STGB;
        const uint32_t bB = sB0 + (it & 1) * STGB;
#pragma unroll
        for (int ks = 0; ks < 4; ks++) {
            uint32_t bf[4][2];
#pragma unroll
            for (int np = 0; np < 2; np++)
                LDSM4(bf[2 * np][0], bf[2 * np][1], bf[2 * np + 1][0], bf[2 * np + 1][1],
                      bB + bOff[np] + ks * 32);
#pragma unroll
            for (int mt = 0; mt < 4; mt++) {
                uint32_t af[4];
                LDSM4(af[0], af[1], af[2], af[3], aB + aOff[mt] + ks * 32);
#pragma unroll
                for (int nt = 0; nt < 4; nt++) MMA_F16(c[mt][nt], af, bf[nt]);
            }
        }

        if (kc == 15) {
            const int jt = it >> 4;
            const float* hb8 = shb + jt * 128;
            const float* ws8 = sws + jt * 128;
#pragma unroll
            for (int mt = 0; mt < 4; mt++) {
                float rs0 = 0.f, rs1 = 0.f;
#pragma unroll
                for (int nt = 0; nt < 4; nt++) {
                    int nl = wn * 32 + nt * 8 + tg * 2;
#pragma unroll
                    for (int cc = 0; cc < 2; cc++) {
                        float hb = hb8[nl + cc], ws = ws8[nl + cc];
                        rs0 += htanh(c[mt][nt][cc] + hb) * ws;
                        rs1 += htanh(c[mt][nt][2 + cc] + hb) * ws;
                    }
                }
                rs0 += __shfl_xor_sync(0xffffffffu, rs0, 1);
                rs0 += __shfl_xor_sync(0xffffffffu, rs0, 2);
                rs1 += __shfl_xor_sync(0xffffffffu, rs1, 1);
                rs1 += __shfl_xor_sync(0xffffffffu, rs1, 2);
                rowacc[mt][0] += rs0;
                rowacc[mt][1] += rs1;
#pragma unroll
                for (int nt = 0; nt < 4; nt++)
#pragma unroll
                    for (int d = 0; d < 4; d++) c[mt][nt][d] = 0.f;
            }
        }

        sa = (sa == 2) ? 0 : sa + 1;
        sa2 = (sa2 == 2) ? 0 : sa2 + 1;
    }

#pragma unroll
    for (int mt = 0; mt < 4; mt++) {
        if (tg == 0) {
            atomicAdd(&srow[wm * 64 + mt * 16 + g], rowacc[mt][0]);
            atomicAdd(&srow[wm * 64 + mt * 16 + 8 + g], rowacc[mt][1]);
        }
    }
    __syncthreads();
    if (tid < 128) g_s[R0 + tid] = srow[tid];
}

// ---------------- k_softmax ---------------------------------------------------
__global__ void k_softmax(const float* __restrict__ bs) {
    __shared__ float sv[SRC];
    __shared__ float red[256];
    int b = blockIdx.x, tid = threadIdx.x;
    float bsv = bs[0];
    float lmax = -1e30f;
    for (int t = tid; t < SRC; t += 256) {
        float s = bsv + g_s[b * SRC + t];
        sv[t] = s;
        lmax = fmaxf(lmax, s);
    }
    red[tid] = lmax;
    __syncthreads();
    for (int off = 128; off; off >>= 1) {
        if (tid < off) red[tid] = fmaxf(red[tid], red[tid + off]);
        __syncthreads();
    }
    float m = red[0];
    __syncthreads();
    float lsum = 0.f;
    for (int t = tid; t < SRC; t += 256) {
        float e = __expf(sv[t] - m);
        sv[t] = e;
        lsum += e;
    }
    red[tid] = lsum;
    __syncthreads();
    for (int off = 128; off; off >>= 1) {
        if (tid < off) red[tid] += red[tid + off];
        __syncthreads();
    }
    float inv = 1.f / red[0];
    for (int t = tid; t < SRC; t += 256) g_w[b * SRC + t] = sv[t] * inv;
}

// ---------------- k_ctx : 16-way segmented weighted sum, half2 loads ---------
__global__ void k_ctx() {
    __shared__ float sw[128];
    int b = blockIdx.y, seg = blockIdx.z;
    int k2 = blockIdx.x * 256 + threadIdx.x;
    int t0 = seg * 128;
    if (threadIdx.x < 128) sw[threadIdx.x] = g_w[b * SRC + t0 + threadIdx.x];
    __syncthreads();
    const __half2* ep = reinterpret_cast<const __half2*>(
                            g_encH + ((size_t)b * SRC + t0) * ENCD) + k2;
    float ax0 = 0.f, ay0 = 0.f, ax1 = 0.f, ay1 = 0.f;
    float ax2 = 0.f, ay2 = 0.f, ax3 = 0.f, ay3 = 0.f;
    for (int t = 0; t < 128; t += 8) {
#pragma unroll
        for (int u = 0; u < 8; u += 4) {
            float2 v0 = __half22float2(ep[(size_t)(t + u) * (ENCD / 2)]);
            float2 v1 = __half22float2(ep[(size_t)(t + u + 1) * (ENCD / 2)]);
            float2 v2 = __half22float2(ep[(size_t)(t + u + 2) * (ENCD / 2)]);
            float2 v3 = __half22float2(ep[(size_t)(t + u + 3) * (ENCD / 2)]);
            float w0 = sw[t + u], w1 = sw[t + u + 1];
            float w2 = sw[t + u + 2], w3 = sw[t + u + 3];
            ax0 += w0 * v0.x; ay0 += w0 * v0.y;
            ax1 += w1 * v1.x; ay1 += w1 * v1.y;
            ax2 += w2 * v2.x; ay2 += w2 * v2.y;
            ax3 += w3 * v3.x; ay3 += w3 * v3.y;
        }
    }
    g_ctxp[seg][b][2 * k2] = (ax0 + ax1) + (ax2 + ax3);
    g_ctxp[seg][b][2 * k2 + 1] = (ay0 + ay1) + (ay2 + ay3);
}

// ---------------- k_xin : xin = concat(sum(ctx partials), emb[x]), float4 ----
__global__ void k_xin(const int* __restrict__ x, const float* __restrict__ emb) {
    int b = blockIdx.x;
    int xi = x[b];
    for (int i4 = threadIdx.x; i4 < IN0 / 4; i4 += 256) {
        float4 v;
        if (i4 < ENCD / 4) {
            v = make_float4(0.f, 0.f, 0.f, 0.f);
#pragma unroll
            for (int seg = 0; seg < NSEG; seg++) {
                float4 p = *reinterpret_cast<const float4*>(&g_ctxp[seg][b][i4 * 4]);
                v.x += p.x; v.y += p.y; v.z += p.z; v.w += p.w;
            }
        } else {
            v = *reinterpret_cast<const float4*>(
                    emb + (size_t)xi * EE + (i4 * 4 - ENCD));
        }
        *reinterpret_cast<float4*>(&g_xin[b * IN0 + i4 * 4]) = v;
    }
}

// ---------------- tf32 GEMM body, 4-stage cp.async, cvt-in-fragment ---------
#define GA_W (64 * 36)
#define GB_W (32 * 132)
#define GB_SMEM (4 * (GA_W + GB_W) * 4)

template <int EPI>
__device__ __forceinline__ void gemm_body(const float* __restrict__ A,
                                          const float* __restrict__ B,
                                          const float* __restrict__ bias,
                                          float* __restrict__ C,
                                          int lda, int Kloop, int N, int col0) {
    extern __shared__ float gsm[];
    float* sA4 = gsm;
    float* sB4 = gsm + 4 * GA_W;
    const int tid = threadIdx.x;
    const int wid = tid >> 5, lane = tid & 31;
    const int wm = wid & 1, wn = wid >> 1;
    const int g = lane >> 2, tg = lane & 3;

    const uint32_t a0 = smem_u32(sA4);
    const uint32_t b0 = smem_u32(sB4);

    auto load_kc = [&](int kc) {
        int s = kc & 3;
        int k0 = kc * 32;
        uint32_t aDst = a0 + s * (GA_W * 4);
        uint32_t bDst = b0 + s * (GB_W * 4);
#pragma unroll
        for (int i = 0; i < 2; i++) {
            int idx = tid + i * 256;
            int row = idx >> 3, seg = idx & 7;
            cp16(aDst + (row * 36 + seg * 4) * 4, A + (size_t)row * lda + k0 + seg * 4);
        }
#pragma unroll
        for (int i = 0; i < 4; i++) {
            int idx = tid + i * 256;
            int rb = idx >> 5, c4 = idx & 31;
            cp16(bDst + (rb * 132 + c4 * 4) * 4, B + (size_t)(k0 + rb) * N + col0 + c4 * 4);
        }
    };

    float c[2][4][4];
#pragma unroll
    for (int a = 0; a < 2; a++)
#pragma unroll
        for (int b2 = 0; b2 < 4; b2++)
#pragma unroll
            for (int d = 0; d < 4; d++) c[a][b2][d] = 0.f;

    const int NK = Kloop / 32;
    load_kc(0); CP_COMMIT();
    if (NK > 1) load_kc(1);
    CP_COMMIT();
    if (NK > 2) load_kc(2);
    CP_COMMIT();

    for (int kc = 0; kc < NK; kc++) {
        int s = kc & 3;
        CP_WAIT2();
        __syncthreads();
        if (kc + 3 < NK) load_kc(kc + 3);
        CP_COMMIT();

        const float* pA = sA4 + s * GA_W;
        const float* pB = sB4 + s * GB_W;
#pragma unroll
        for (int ks = 0; ks < 4; ks++) {
            const int kb = ks * 8;
            unsigned af[2][4], bf[4][2];
#pragma unroll
            for (int mt = 0; mt < 2; mt++) {
                int r = wm * 32 + mt * 16 + g;
                af[mt][0] = f2tf32(pA[r * 36 + kb + tg]);
                af[mt][1] = f2tf32(pA[(r + 8) * 36 + kb + tg]);
                af[mt][2] = f2tf32(pA[r * 36 + kb + tg + 4]);
                af[mt][3] = f2tf32(pA[(r + 8) * 36 + kb + tg + 4]);
            }
#pragma unroll
            for (int nt = 0; nt < 4; nt++) {
                int col = wn * 32 + nt * 8 + g;
                bf[nt][0] = f2tf32(pB[(kb + tg) * 132 + col]);
                bf[nt][1] = f2tf32(pB[(kb + tg + 4) * 132 + col]);
            }
#pragma unroll
            for (int mt = 0; mt < 2; mt++)
#pragma unroll
                for (int nt = 0; nt < 4; nt++) MMA_TF32(c[mt][nt], af[mt], bf[nt]);
        }
    }
#pragma unroll
    for (int mt = 0; mt < 2; mt++)
#pragma unroll
        for (int nt = 0; nt < 4; nt++) {
            int r = wm * 32 + mt * 16 + g;
            int col = col0 + wn * 32 + nt * 8 + tg * 2;
            float add0 = 0.f, add1 = 0.f;
            if (EPI == 1) { add0 = bias[col]; add1 = bias[col + 1]; }
            C[(size_t)r * N + col] = c[mt][nt][0] + add0;
            C[(size_t)r * N + col + 1] = c[mt][nt][1] + add1;
            C[(size_t)(r + 8) * N + col] = c[mt][nt][2] + add0;
            C[(size_t)(r + 8) * N + col + 1] = c[mt][nt][3] + add1;
        }
}

template <int EPI>
__global__ __launch_bounds__(256, 2) void k_gemm(const float* __restrict__ A,
                                                 const float* __restrict__ B,
                                                 const float* __restrict__ bias,
                                                 float* __restrict__ C, int K, int N) {
    gemm_body<EPI>(A, B, bias, C, K, K, N, blockIdx.x * 128);
}

// h-GEMM: h_partial[z] = state @ Wh[z-quarter]; grid (8, 1, HSPLIT)
__global__ __launch_bounds__(256, 2) void k_hgemm(const float* __restrict__ state,
                                                  const float* __restrict__ Wh,
                                                  float* __restrict__ hp) {
    const int z = blockIdx.z;
    const int Ks = UU / HSPLIT;     // 256
    gemm_body<0>(state + z * Ks, Wh + (size_t)z * Ks * UU,
                 nullptr, hp + (size_t)z * BB * UU, UU, Ks, UU, blockIdx.x * 128);
}

// split-K paired GEMM: grid (N/128, 2 pairs, NSPLIT splits)
__global__ __launch_bounds__(256, 2) void k_gemm_splitk(
    const float* A0, const float* A1, const float* B0, const float* B1,
    float* Cp, int K, int N) {
    const int pair = blockIdx.y, z = blockIdx.z;
    const float* A = pair ? A1 : A0;
    const float* B = pair ? B1 : B0;
    const int Ks = K / NSPLIT;
    float* C = Cp + ((size_t)z * 2 + pair) * XSEG;
    gemm_body<0>(A + z * Ks, B + (size_t)z * Ks * N, nullptr, C,
                 K, Ks, N, blockIdx.x * 128);
}

// ---------------- k_gru_pair : sums NSPLIT split-K partials + pointwise GRU --
__global__ void k_gru_pair(const float* xgp, const float* b0v, const float* b1v,
                           float* o0, float* o1, float* y0, float* y1) {
    const int pair = blockIdx.y;
    const float* xg = xgp + (size_t)pair * XSEG;
    const float* bvec = pair ? b1v : b0v;
    float* hout = pair ? o1 : o0;
    float* yout = pair ? y1 : y0;
    int b = blockIdx.x;
    const size_t ZS = 2 * (size_t)XSEG;
    int u = threadIdx.x * 4;
    size_t iz = (size_t)b * 3 * UU + u;
    size_t ir = iz + UU, ih = iz + 2 * UU;

    float4 xz = make_float4(0.f, 0.f, 0.f, 0.f);
    float4 xr = xz, xh = xz;
#pragma unroll
    for (int z = 0; z < NSPLIT; z++) {
        float4 pz = *reinterpret_cast<const float4*>(xg + iz + z * ZS);
        float4 pr = *reinterpret_cast<const float4*>(xg + ir + z * ZS);
        float4 ph = *reinterpret_cast<const float4*>(xg + ih + z * ZS);
        xz.x += pz.x; xz.y += pz.y; xz.z += pz.z; xz.w += pz.w;
        xr.x += pr.x; xr.y += pr.y; xr.z += pr.z; xr.w += pr.w;
        xh.x += ph.x; xh.y += ph.y; xh.z += ph.z; xh.w += ph.w;
    }
    float4 b0z = *reinterpret_cast<const float4*>(bvec + u);
    float4 b0r = *reinterpret_cast<const float4*>(bvec + UU + u);
    float4 b0h = *reinterpret_cast<const float4*>(bvec + 2 * UU + u);
    float4 b1z = *reinterpret_cast<const float4*>(bvec + 3 * UU + u);
    float4 b1r = *reinterpret_cast<const float4*>(bvec + 3 * UU + UU + u);
    float4 b1h = *reinterpret_cast<const float4*>(bvec + 3 * UU + 2 * UU + u);

    float4 hres;
    {
        float vz[4] = {xz.x + b0z.x + b1z.x, xz.y + b0z.y + b1z.y,
                       xz.z + b0z.z + b1z.z, xz.w + b0z.w + b1z.w};
        float vr[4] = {xr.x + b0r.x + b1r.x, xr.y + b0r.y + b1r.y,
                       xr.z + b0r.z + b1r.z, xr.w + b0r.w + b1r.w};
        float vh[4] = {xh.x + b0h.x, xh.y + b0h.y, xh.z + b0h.z, xh.w + b0h.w};
        float v1h[4] = {b1h.x, b1h.y, b1h.z, b1h.w};
        float* hr = reinterpret_cast<float*>(&hres);
#pragma unroll
        for (int q = 0; q < 4; q++) {
            float z = 1.f / (1.f + __expf(-vz[q]));
            float r = 1.f / (1.f + __expf(-vr[q]));
            float hc = tanhf(vh[q] + r * v1h[q]);
            hr[q] = (1.f - z) * hc;
        }
    }
    *reinterpret_cast<float4*>(hout + b * UU + u) = hres;
    if (yout) *reinterpret_cast<float4*>(yout + b * 2 * UU + u) = hres;
}

// ---------------- host launcher ----------------------------------------------
extern "C" void kernel_launch(void* const* d_in, const int* in_sizes, int n_in,
                              void* d_out, int out_size) {
    (void)in_sizes; (void)n_in; (void)out_size;
    const int* x = (const int*)d_in[0];
    const float* state = (const float*)d_in[1];
    const float* enc = (const float*)d_in[2];
    const float* Wh = (const float*)d_in[3];
    const float* bh = (const float*)d_in[4];
    const float* Wc = (const float*)d_in[5];
    const float* bc = (const float*)d_in[6];
    const float* Ws = (const float*)d_in[7];
    const float* bs = (const float*)d_in[8];
    const float* emb = (const float*)d_in[9];
    const float* fw0_k = (const float*)d_in[10];
    const float* fw0_b = (const float*)d_in[12];
    const float* fw1_k = (const float*)d_in[13];
    const float* fw1_b = (const float*)d_in[15];
    const float* bw0_k = (const float*)d_in[16];
    const float* bw0_b = (const float*)d_in[18];
    const float* bw1_k = (const float*)d_in[19];
    const float* bw1_b = (const float*)d_in[21];
    const float* fcW = (const float*)d_in[22];
    const float* fcb = (const float*)d_in[23];

    float* out = (float*)d_out;
    float* h0f = out + (size_t)BB * VV;
    float* h1f = h0f + BB * UU;
    float* h0b = h1f + BB * UU;
    float* h1b = h0b + BB * UU;

    float *p_xin, *p_xgp, *p_y;
    cudaGetSymbolAddress((void**)&p_xin, g_xin);
    cudaGetSymbolAddress((void**)&p_xgp, g_xgp);
    cudaGetSymbolAddress((void**)&p_y, g_y);

    cudaFuncSetAttribute(k_score, cudaFuncAttributeMaxDynamicSharedMemorySize, SC_SMEM);
    cudaFuncSetAttribute(k_gemm<1>, cudaFuncAttributeMaxDynamicSharedMemorySize, GB_SMEM);
    cudaFuncSetAttribute(k_hgemm, cudaFuncAttributeMaxDynamicSharedMemorySize, GB_SMEM);
    cudaFuncSetAttribute(k_gemm_splitk, cudaFuncAttributeMaxDynamicSharedMemorySize, GB_SMEM);

    // attention: h via split-K tf32 GEMM (partials in p_xgp); Wc transpose;
    // k_score prologue sums the HSPLIT h-partials + bh + bc into shb.
    k_hgemm<<<dim3(UU / 128, 1, HSPLIT), 256, GB_SMEM>>>(state, Wh, p_xgp);
    k_prep<<<1024, 256>>>(Wc);
    k_score<<<MROWS / 128, 256, SC_SMEM>>>(enc, p_xgp, bh, bc, Ws);
    k_softmax<<<BB, 256>>>(bs);
    k_ctx<<<dim3(ENCD / 512, BB, NSEG), 256>>>();
    k_xin<<<BB, 256>>>(x, emb);

    // GRU stacks (zero hidden state => rk unused); fw/bw paired, split-K x8
    // (p_xgp h-partials are consumed by k_score before this overwrites them)
    k_gemm_splitk<<<dim3(3 * UU / 128, 2, NSPLIT), 256, GB_SMEM>>>(
        p_xin, p_xin, fw0_k, bw0_k, p_xgp, IN0, 3 * UU);
    k_gru_pair<<<dim3(BB, 2), 256>>>(p_xgp, fw0_b, bw0_b, h0f, h0b, nullptr, nullptr);
    k_gemm_splitk<<<dim3(3 * UU / 128, 2, NSPLIT), 256, GB_SMEM>>>(
        h0f, h0b, fw1_k, bw1_k, p_xgp, UU, 3 * UU);
    k_gru_pair<<<dim3(BB, 2), 256>>>(p_xgp, fw1_b, bw1_b, h1f, h1b,
                                     p_y, p_y + UU);

    // output projection
    k_gemm<1><<<dim3(VV / 128, 1), 256, GB_SMEM>>>(p_y, fcW, fcb, out, 2 * UU, VV);
}